// round 11
// baseline (speedup 1.0000x reference)
#include <cuda_runtime.h>
#include <math.h>
#include <stdint.h>

#define BN   2
#define TT   256
#define HID  2048
#define NOUT 2048
#define NH   16
#define HD   128
#define BH   32
#define CS   8
#define NC   32
#define NCG  8
#define MROWS (BN*TT)

typedef unsigned long long ull;

// ------------------------- scratch (device globals) -------------------------
__device__ float g_Q[BH*TT*HD];
__device__ float g_K[BH*TT*HD];
__device__ float g_V[BH*TT*HD];
__device__ float g_Of[MROWS*HID];
__device__ float g_g[BH*TT];
__device__ float g_beta[BH*TT];
__device__ float g_Skk[BH*NC*HD*HD];
__device__ float g_Skv[BH*NC*HD*HD];

// ------------------------- helpers -------------------------
__device__ __forceinline__ float warp_sum(float v){
#pragma unroll
  for (int o = 16; o; o >>= 1) v += __shfl_xor_sync(0xffffffffu, v, o);
  return v;
}
__device__ __forceinline__ ull bcast2(float x){
  ull r; asm("mov.b64 %0, {%1, %1};" : "=l"(r) : "f"(x)); return r;
}
__device__ __forceinline__ void ffma2(ull& d, ull a, ull b){
  asm("fma.rn.f32x2 %0, %1, %2, %0;" : "+l"(d) : "l"(a), "l"(b));
}
__device__ __forceinline__ float2 unpack2(ull v){
  float2 f; asm("mov.b64 {%0, %1}, %2;" : "=f"(f.x), "=f"(f.y) : "l"(v)); return f;
}
__device__ __forceinline__ float silu(float z){ return z / (1.f + expf(-z)); }
__device__ __forceinline__ void group_bar(int g){
  asm volatile("bar.sync %0, %1;" :: "r"(1 + g), "r"(128) : "memory");
}
__device__ __forceinline__ uint32_t f2tf32(float v){
  uint32_t r; asm("cvt.rna.tf32.f32 %0, %1;" : "=r"(r) : "f"(v)); return r;
}

#define MMA_TF32(d, a0,a1,a2,a3, b0,b1) \
  asm volatile("mma.sync.aligned.m16n8k8.row.col.f32.tf32.tf32.f32 " \
    "{%0,%1,%2,%3}, {%4,%5,%6,%7}, {%8,%9}, {%0,%1,%2,%3};" \
    : "+f"((d)[0]),"+f"((d)[1]),"+f"((d)[2]),"+f"((d)[3]) \
    : "r"(a0),"r"(a1),"r"(a2),"r"(a3), "r"(b0),"r"(b1))

// ------------------------- K1: QKV GEMM (3xTF32) + SiLU + l2 + fused gates ----
union QkvSmem {
  struct {
    uint32_t Ah[64][20], Al[64][20];
    uint32_t Bh[16][136], Bl[16][136];
    float l2s[64][4];
  } g;
  struct {
    float xr[HID];
    float red[8][32];
  } gate;
};

__global__ void __launch_bounds__(256,2) k_qkv(const float* __restrict__ X,
                                               const float* __restrict__ Wq,
                                               const float* __restrict__ Wk,
                                               const float* __restrict__ Wv,
                                               const float* __restrict__ Wa,
                                               const float* __restrict__ ba,
                                               const float* __restrict__ Wb,
                                               const float* __restrict__ bb){
  int z = blockIdx.z;
  int tid = threadIdx.x;
  __shared__ __align__(16) QkvSmem S;

  if (z == 3){
    // ---- gates path ----
    float* xr = S.gate.xr;
    int cta = blockIdx.y * 16 + blockIdx.x;     // 0..127
    for (int r4 = 0; r4 < 4; r4++){
      int row = cta*4 + r4;
      int b = row >> 8, t = row & 255;
      const float4* xp = (const float4*)(X + (size_t)row * HID);
      for (int idx = tid; idx < HID/4; idx += 256)
        *(float4*)&xr[idx*4] = xp[idx];
      __syncthreads();
      int o = tid & 31, k8 = tid >> 5;
      float partial = 0.f;
      if (o < 16){
        for (int cc = k8*256; cc < k8*256+256; cc++) partial += xr[cc] * Wa[cc*NH + o];
      } else {
        int oo = o - 16;
        for (int cc = k8*256; cc < k8*256+256; cc++) partial += xr[cc] * Wb[cc*NH + oo];
      }
      S.gate.red[k8][o] = partial;
      __syncthreads();
      if (tid < 32){
        float v = 0.f;
#pragma unroll
        for (int u = 0; u < 8; u++) v += S.gate.red[u][tid];
        if (tid < 16){
          float zz = v + ba[tid];
          float ls = (zz >= 0.f) ? -log1pf(expf(-zz)) : (zz - log1pf(expf(zz)));
          g_g[(b*NH + tid)*TT + t] = ls;
        } else {
          int hh = tid - 16;
          float zz = v + bb[hh];
          g_beta[(b*NH + hh)*TT + t] = 1.f / (1.f + expf(-zz));
        }
      }
      __syncthreads();
    }
    return;
  }

  const float* W = z == 0 ? Wq : (z == 1 ? Wk : Wv);
  float* DST     = z == 0 ? g_Q : (z == 1 ? g_K : g_V);

  int lane = tid & 31, warp = tid >> 5;
  int wr = warp >> 2, wn = warp & 3;
  int g = lane >> 2, cq = lane & 3;
  int m0 = blockIdx.y * 64;
  int h = blockIdx.x;
  int n0 = h * 128;

  float acc[2][4][4];
#pragma unroll
  for (int mt = 0; mt < 2; mt++)
#pragma unroll
    for (int nt = 0; nt < 4; nt++)
#pragma unroll
      for (int j = 0; j < 4; j++) acc[mt][nt][j] = 0.f;

  int am = tid >> 2, ak = (tid & 3) * 4;
  int bk0 = tid >> 5, bn0 = (tid & 31) * 4;
  float4 pa, pb[2];
  pa = *(const float4*)&X[(size_t)(m0 + am)*HID + ak];
#pragma unroll
  for (int p = 0; p < 2; p++)
    pb[p] = *(const float4*)&W[(size_t)(bk0 + p*8)*NOUT + n0 + bn0];

  for (int kb = 0; kb < HID; kb += 16){
    {
      float vv[4] = {pa.x, pa.y, pa.z, pa.w};
      uint32_t hi[4], lo[4];
#pragma unroll
      for (int e = 0; e < 4; e++){
        hi[e] = f2tf32(vv[e]);
        lo[e] = f2tf32(vv[e] - __uint_as_float(hi[e]));
      }
      *(uint4*)&S.g.Ah[am][ak] = make_uint4(hi[0], hi[1], hi[2], hi[3]);
      *(uint4*)&S.g.Al[am][ak] = make_uint4(lo[0], lo[1], lo[2], lo[3]);
#pragma unroll
      for (int p = 0; p < 2; p++){
        float wv[4] = {pb[p].x, pb[p].y, pb[p].z, pb[p].w};
#pragma unroll
        for (int e = 0; e < 4; e++){
          hi[e] = f2tf32(wv[e]);
          lo[e] = f2tf32(wv[e] - __uint_as_float(hi[e]));
        }
        *(uint4*)&S.g.Bh[bk0 + p*8][bn0] = make_uint4(hi[0], hi[1], hi[2], hi[3]);
        *(uint4*)&S.g.Bl[bk0 + p*8][bn0] = make_uint4(lo[0], lo[1], lo[2], lo[3]);
      }
    }
    __syncthreads();
    if (kb + 16 < HID){
      pa = *(const float4*)&X[(size_t)(m0 + am)*HID + kb + 16 + ak];
#pragma unroll
      for (int p = 0; p < 2; p++)
        pb[p] = *(const float4*)&W[(size_t)(kb + 16 + bk0 + p*8)*NOUT + n0 + bn0];
    }
#pragma unroll
    for (int ks = 0; ks < 2; ks++){
      int k0 = ks*8 + cq;
      uint32_t ah[2][4], al[2][4];
#pragma unroll
      for (int mt = 0; mt < 2; mt++){
        int mb = wr*32 + mt*16;
        ah[mt][0] = S.g.Ah[mb+g][k0];   ah[mt][1] = S.g.Ah[mb+g+8][k0];
        ah[mt][2] = S.g.Ah[mb+g][k0+4]; ah[mt][3] = S.g.Ah[mb+g+8][k0+4];
        al[mt][0] = S.g.Al[mb+g][k0];   al[mt][1] = S.g.Al[mb+g+8][k0];
        al[mt][2] = S.g.Al[mb+g][k0+4]; al[mt][3] = S.g.Al[mb+g+8][k0+4];
      }
#pragma unroll
      for (int nt = 0; nt < 4; nt++){
        int nb = wn*32 + nt*8;
        uint32_t bh0 = S.g.Bh[k0][nb+g], bh1 = S.g.Bh[k0+4][nb+g];
        uint32_t bl0 = S.g.Bl[k0][nb+g], bl1 = S.g.Bl[k0+4][nb+g];
#pragma unroll
        for (int mt = 0; mt < 2; mt++){
          MMA_TF32(acc[mt][nt], ah[mt][0], ah[mt][1], ah[mt][2], ah[mt][3], bl0, bl1);
          MMA_TF32(acc[mt][nt], al[mt][0], al[mt][1], al[mt][2], al[mt][3], bh0, bh1);
          MMA_TF32(acc[mt][nt], ah[mt][0], ah[mt][1], ah[mt][2], ah[mt][3], bh0, bh1);
        }
      }
    }
    __syncthreads();
  }

  float v[2][4][4];
#pragma unroll
  for (int mt = 0; mt < 2; mt++)
#pragma unroll
    for (int nt = 0; nt < 4; nt++)
#pragma unroll
      for (int j = 0; j < 4; j++) v[mt][nt][j] = silu(acc[mt][nt][j]);

  float scale[2][2] = {{1.f,1.f},{1.f,1.f}};
  if (z < 2){
#pragma unroll
    for (int mt = 0; mt < 2; mt++){
      float s0 = 0.f, s1 = 0.f;
#pragma unroll
      for (int nt = 0; nt < 4; nt++){
        s0 += v[mt][nt][0]*v[mt][nt][0] + v[mt][nt][1]*v[mt][nt][1];
        s1 += v[mt][nt][2]*v[mt][nt][2] + v[mt][nt][3]*v[mt][nt][3];
      }
      s0 += __shfl_xor_sync(0xffffffffu, s0, 1);
      s0 += __shfl_xor_sync(0xffffffffu, s0, 2);
      s1 += __shfl_xor_sync(0xffffffffu, s1, 1);
      s1 += __shfl_xor_sync(0xffffffffu, s1, 2);
      if (cq == 0){
        S.g.l2s[wr*32 + mt*16 + g][wn]     = s0;
        S.g.l2s[wr*32 + mt*16 + g + 8][wn] = s1;
      }
    }
    __syncthreads();
#pragma unroll
    for (int mt = 0; mt < 2; mt++){
      float4 q0 = *(const float4*)&S.g.l2s[wr*32 + mt*16 + g][0];
      float4 q1 = *(const float4*)&S.g.l2s[wr*32 + mt*16 + g + 8][0];
      float s0 = (q0.x + q0.y) + (q0.z + q0.w);
      float s1 = (q1.x + q1.y) + (q1.z + q1.w);
      scale[mt][0] = 1.f / fmaxf(sqrtf(s0), 1e-12f);
      scale[mt][1] = 1.f / fmaxf(sqrtf(s1), 1e-12f);
    }
  }

#pragma unroll
  for (int mt = 0; mt < 2; mt++){
    int m = m0 + wr*32 + mt*16 + g;
    int b = m >> 8, t = m & 255;
#pragma unroll
    for (int nt = 0; nt < 4; nt++){
      int d = wn*32 + nt*8 + cq*2;
      size_t off = ((size_t)((b*NH + h)*TT + t))*HD + d;
      *(float2*)&DST[off] = make_float2(v[mt][nt][0]*scale[mt][0],
                                        v[mt][nt][1]*scale[mt][0]);
      *(float2*)&DST[off + 8*HD] = make_float2(v[mt][nt][2]*scale[mt][1],
                                               v[mt][nt][3]*scale[mt][1]);
    }
  }
}

// ------------------------- K2: chunk sums + scan fused ------------------------
__global__ void __launch_bounds__(256,4) k_chunkscan(){
  int vslab = blockIdx.x, bh = blockIdx.y;
  int tid = threadIdx.x;
  int i  = vslab*16 + (tid >> 4);
  int j0 = (tid & 15) * 8;
  __shared__ __align__(16) float ks[CS][HD], vs[CS][HD];
  __shared__ float coef[CS];
  __shared__ float dcs;
  float ckk[8], ckv[8];
#pragma unroll
  for (int u = 0; u < 8; u++){ ckk[u] = 0.f; ckv[u] = 0.f; }

  for (int c = 0; c < NC; c++){
    if (c) __syncthreads();
    {
      const float4* Kp = (const float4*)(g_K + (size_t)(bh*TT + c*CS)*HD);
      const float4* Vp = (const float4*)(g_V + (size_t)(bh*TT + c*CS)*HD);
      ((float4*)ks)[tid] = Kp[tid];
      ((float4*)vs)[tid] = Vp[tid];
    }
    if (tid < CS){
      float s = 0.f;
      for (int u = tid + 1; u < CS; u++) s += g_g[bh*TT + c*CS + u];
      coef[tid] = g_beta[bh*TT + c*CS + tid] * expf(s);
    }
    if (tid == 8){
      float s = 0.f;
      for (int u = 0; u < CS; u++) s += g_g[bh*TT + c*CS + u];
      dcs = expf(s);
    }
    __syncthreads();
    float dc = dcs;
#pragma unroll
    for (int u = 0; u < 8; u++){ ckk[u] *= dc; ckv[u] *= dc; }
#pragma unroll
    for (int s = 0; s < CS; s++){
      float ki = ks[s][i] * coef[s];
      float4 ka = *(const float4*)&ks[s][j0];
      float4 kb = *(const float4*)&ks[s][j0+4];
      float4 va = *(const float4*)&vs[s][j0];
      float4 vb = *(const float4*)&vs[s][j0+4];
      ckk[0] += ki*ka.x; ckk[1] += ki*ka.y; ckk[2] += ki*ka.z; ckk[3] += ki*ka.w;
      ckk[4] += ki*kb.x; ckk[5] += ki*kb.y; ckk[6] += ki*kb.z; ckk[7] += ki*kb.w;
      ckv[0] += ki*va.x; ckv[1] += ki*va.y; ckv[2] += ki*va.z; ckv[3] += ki*va.w;
      ckv[4] += ki*vb.x; ckv[5] += ki*vb.y; ckv[6] += ki*vb.z; ckv[7] += ki*vb.w;
    }
    size_t base = ((size_t)(bh*NC + c) << 14) + (size_t)i*HD + j0;
    *(float4*)&g_Skk[base]   = make_float4(ckk[0], ckk[1], ckk[2], ckk[3]);
    *(float4*)&g_Skk[base+4] = make_float4(ckk[4], ckk[5], ckk[6], ckk[7]);
    *(float4*)&g_Skv[base]   = make_float4(ckv[0], ckv[1], ckv[2], ckv[3]);
    *(float4*)&g_Skv[base+4] = make_float4(ckv[4], ckv[5], ckv[6], ckv[7]);
  }
}

// ------------------------- K3: batched 8-RHS CG solve (256 thr, 2 CTAs/SM) ----
#define PHASE_A(MSM) do { \
  ull y0a=0ull, y0b=0ull, y0c=0ull, y0d=0ull; \
  ull y1a=0ull, y1b=0ull, y1c=0ull, y1d=0ull; \
  _Pragma("unroll") \
  for (int jj = 0; jj < 32; jj++){ \
    ulonglong2 pA = *(const ulonglong2*)&P[mq*32+jj][0]; \
    ulonglong2 pB = *(const ulonglong2*)&P[mq*32+jj][4]; \
    ull h0 = bcast2(hk[jj]); \
    ull h1 = bcast2(hk[32+jj]); \
    ffma2(y0a, h0, pA.x); ffma2(y0b, h0, pA.y); ffma2(y0c, h0, pB.x); ffma2(y0d, h0, pB.y); \
    ffma2(y1a, h1, pA.x); ffma2(y1b, h1, pA.y); ffma2(y1c, h1, pB.x); ffma2(y1d, h1, pB.y); \
  } \
  *(ulonglong2*)&part[mq][mi][0] = make_ulonglong2(y0a, y0b); \
  *(ulonglong2*)&part[mq][mi][4] = make_ulonglong2(y0c, y0d); \
  *(ulonglong2*)&part[mq][mi+64][0] = make_ulonglong2(y1a, y1b); \
  *(ulonglong2*)&part[mq][mi+64][4] = make_ulonglong2(y1c, y1d); \
  { float4 kv_ = *(const float4*)&MSM[warp][lane*4]; \
    _Pragma("unroll") \
    for (int t_ = 0; t_ < 8; t_++){ \
      float4 pv_ = *(const float4*)&PT[t_][lane*4]; \
      float pd_ = kv_.x*pv_.x + kv_.y*pv_.y + kv_.z*pv_.z + kv_.w*pv_.w; \
      pd_ = warp_sum(pd_); \
      if (lane == 0) dots[t_][warp] = pd_; \
    } } \
} while(0)

#define ASM4(OUT) do { \
  float4 ya_ = make_float4(0.f, 0.f, 0.f, 0.f); \
  _Pragma("unroll") \
  for (int q2 = 0; q2 < 4; q2++){ \
    float4 pr_ = *(const float4*)&part[q2][si][t0]; \
    ya_.x += pr_.x; ya_.y += pr_.y; ya_.z += pr_.z; ya_.w += pr_.w; \
  } \
  float yarr_[4] = {ya_.x, ya_.y, ya_.z, ya_.w}; \
  _Pragma("unroll") \
  for (int u = 0; u < 4; u++){ \
    int t_ = t0 + u; \
    float a_ = cdec[t_] * yarr_[u]; \
    float4 d0_ = *(const float4*)&dots[t_][0]; \
    float4 d1_ = *(const float4*)&dots[t_][4]; \
    float4 w0_ = *(const float4*)&Wc[t_][0]; \
    float4 w1_ = *(const float4*)&Wc[t_][4]; \
    a_ += (w0_.x*d0_.x)*ksi[0] + (w0_.y*d0_.y)*ksi[1] \
        + (w0_.z*d0_.z)*ksi[2] + (w0_.w*d0_.w)*ksi[3] \
        + (w1_.x*d1_.x)*ksi[4] + (w1_.y*d1_.y)*ksi[5] \
        + (w1_.z*d1_.z)*ksi[6] + (w1_.w*d1_.w)*ksi[7]; \
    OUT[u] = a_; \
  } \
} while(0)

__global__ void __launch_bounds__(256,2) k_solve(const float* __restrict__ lp,
                                                 const float* __restrict__ onw){
  int c = blockIdx.x, bh = blockIdx.y;
  int b = bh >> 4, h = bh & 15;
  int tid = threadIdx.x;
  int si = tid & 127, sg2 = tid >> 7, lane = tid & 31, warp = tid >> 5;
  int mi = tid & 63, mq = tid >> 6;
  int g0 = bh*TT + c*CS;
  int t0 = sg2*4;

  __shared__ __align__(16) float Ksm[CS][HD], Vsm[CS][HD], Qsm[CS][HD];
  __shared__ __align__(16) float P[HD][12];
  __shared__ __align__(16) float PT[CS][HD+4];
  __shared__ __align__(16) float part[4][HD][12];
  __shared__ __align__(16) float dots[CS][CS];
  __shared__ __align__(16) float Wc[CS][CS];
  __shared__ float cdec[CS];
  __shared__ float lam[HD], dg[HD], gsm[CS], bsm[CS];
  __shared__ __align__(16) float wredA[4][8];
  __shared__ __align__(16) float wredB[4][8];

  {
    const float4* Kp = (const float4*)(g_K + (size_t)g0*HD);
    const float4* Vp = (const float4*)(g_V + (size_t)g0*HD);
    const float4* Qp = (const float4*)(g_Q + (size_t)g0*HD);
    ((float4*)Ksm)[tid] = Kp[tid];
    ((float4*)Qsm)[tid] = Qp[tid];
    ((float4*)Vsm)[tid] = Vp[tid];
  }
  if (tid >= 128 && tid < 136){ gsm[tid-128] = g_g[g0 + tid-128]; bsm[tid-128] = g_beta[g0 + tid-128]; }
  if (tid < 128){
    float zz = lp[h*HD + tid];
    float sp = (zz > 20.f) ? zz : log1pf(expf(zz));
    lam[tid] = sp + 0.25f;
  }
  float hk[64];
  if (c == 0){
#pragma unroll
    for (int jj = 0; jj < 64; jj++) hk[jj] = 0.f;
  } else {
    size_t base = ((size_t)(bh*NC + (c-1)) << 14) + mq*32;
#pragma unroll
    for (int jj = 0; jj < 32; jj += 4){
      float4 a = *(const float4*)&g_Skk[base + (size_t)mi*HD + jj];
      hk[jj] = a.x; hk[jj+1] = a.y; hk[jj+2] = a.z; hk[jj+3] = a.w;
      float4 a2 = *(const float4*)&g_Skk[base + (size_t)(mi+64)*HD + jj];
      hk[32+jj] = a2.x; hk[33+jj] = a2.y; hk[34+jj] = a2.z; hk[35+jj] = a2.w;
    }
  }
  if (mq == (mi >> 5))       dg[mi]      = hk[mi & 31];
  if (mq == 2 + (mi >> 5))   dg[mi + 64] = hk[32 + (mi & 31)];
  __syncthreads();

  if (tid < 64){
    int t_ = tid >> 3, s_ = tid & 7;
    float w = 0.f;
    if (s_ <= t_){
      float s = 0.f;
      for (int u = s_+1; u <= t_; u++) s += gsm[u];
      w = bsm[s_] * expf(s);
    }
    Wc[t_][s_] = w;
  }
  if (tid >= 64 && tid < 72){
    int t_ = tid - 64;
    float s = 0.f;
    for (int u = 0; u <= t_; u++) s += gsm[u];
    cdec[t_] = expf(s);
  }
  __syncthreads();

  float ksi[CS];
#pragma unroll
  for (int s = 0; s < CS; s++) ksi[s] = Ksm[s][si];
  float xv[4], rv[4], pv[4], dloc[4], qv[4];
  unsigned dmask = 0;
#pragma unroll
  for (int u = 0; u < 4; u++){
    int t = t0 + u;
    float diag = cdec[t]*dg[si] + lam[si];
#pragma unroll
    for (int s = 0; s < CS; s++) diag += Wc[t][s] * ksi[s] * ksi[s];
    float x = Qsm[t][si] / (diag + 1e-8f);
    xv[u] = x; P[si][t] = x; PT[t][si] = x;
  }
  __syncthreads();

  PHASE_A(Ksm);
  __syncthreads();
  {
    float av[4];
    ASM4(av);
#pragma unroll
    for (int u = 0; u < 4; u++){
      int t = t0 + u;
      float r = Qsm[t][si] - (av[u] + lam[si]*xv[u]);
      rv[u] = r; pv[u] = r;
      float rr = warp_sum(r*r);
      if (lane == 0) wredA[u][warp] = rr;
      P[si][t] = r; PT[t][si] = r;
    }
  }
  group_bar(sg2);
#pragma unroll
  for (int u = 0; u < 4; u++){
    float4 wv = *(const float4*)&wredA[u][sg2*4];
    dloc[u] = (wv.x + wv.y) + (wv.z + wv.w);
  }
  __syncthreads();

  for (int it = 0; it < NCG; it++){
    PHASE_A(Ksm);
    __syncthreads();
    {
      ASM4(qv);
#pragma unroll
      for (int u = 0; u < 4; u++){
        qv[u] += lam[si] * pv[u];
        float pq = warp_sum(pv[u] * qv[u]);
        if (lane == 0) wredA[u][warp] = pq;
      }
    }
    group_bar(sg2);
#pragma unroll
    for (int u = 0; u < 4; u++){
      float4 wv = *(const float4*)&wredA[u][sg2*4];
      float pq = (wv.x + wv.y) + (wv.z + wv.w);
      if (dloc[u] < 1e-10f) dmask |= 1u << u;
      if (fabsf(pq) < 1e-10f) dmask |= 1u << u;
      float alpha = (dmask >> u & 1u) ? 0.f : dloc[u] / pq;
      xv[u] += alpha * pv[u];
      rv[u] -= alpha * qv[u];
      float rr = warp_sum(rv[u] * rv[u]);
      if (lane == 0) wredB[u][warp] = rr;
    }
    group_bar(sg2);
#pragma unroll
    for (int u = 0; u < 4; u++){
      int t = t0 + u;
      float4 wv = *(const float4*)&wredB[u][sg2*4];
      float dn = (wv.x + wv.y) + (wv.z + wv.w);
      if (!(dmask >> u & 1u)){
        float bet = dn / dloc[u];
        dloc[u] = dn;
        pv[u] = rv[u] + bet * pv[u];
      }
      P[si][t] = pv[u]; PT[t][si] = pv[u];
    }
    __syncthreads();
  }

#pragma unroll
  for (int u = 0; u < 4; u++){
    int t = t0 + u;
    P[si][t] = xv[u]; PT[t][si] = xv[u];
  }
  if (c == 0){
#pragma unroll
    for (int jj = 0; jj < 64; jj++) hk[jj] = 0.f;
  } else {
    size_t base = ((size_t)(bh*NC + (c-1)) << 14) + mq*32;
#pragma unroll
    for (int jj = 0; jj < 32; jj += 4){
      float4 a = *(const float4*)&g_Skv[base + (size_t)mi*HD + jj];
      hk[jj] = a.x; hk[jj+1] = a.y; hk[jj+2] = a.z; hk[jj+3] = a.w;
      float4 a2 = *(const float4*)&g_Skv[base + (size_t)(mi+64)*HD + jj];
      hk[32+jj] = a2.x; hk[33+jj] = a2.y; hk[34+jj] = a2.z; hk[35+jj] = a2.w;
    }
  }
  __syncthreads();
  PHASE_A(Vsm);
  __syncthreads();
  float ov[4];
  ASM4(ov);
#pragma unroll
  for (int u = 0; u < 4; u++){
    float ss = warp_sum(ov[u]*ov[u]);
    if (lane == 0) wredA[u][warp] = ss;
  }
  group_bar(sg2);
  float wnv = onw[si];
#pragma unroll
  for (int u = 0; u < 4; u++){
    int t = t0 + u;
    float4 wv = *(const float4*)&wredA[u][sg2*4];
    float ms = ((wv.x + wv.y) + (wv.z + wv.w)) * (1.f/128.f);
    float rms = sqrtf(ms + 1e-6f);
    int ts = c*CS + t;
    g_Of[(size_t)(b*TT + ts)*HID + h*HD + si] = ov[u] / rms * wnv;
  }
}

// ------------------------- K4: output projection (3xTF32, 64x64 tiles) --------
__global__ void __launch_bounds__(256,2) k_out(const float* __restrict__ Wo,
                                               float* __restrict__ out){
  __shared__ __align__(16) uint32_t Ah[64][20], Al[64][20];
  __shared__ __align__(16) uint32_t Bh[16][72], Bl[16][72];

  int tid = threadIdx.x;
  int lane = tid & 31, warp = tid >> 5;
  int wr = warp >> 2, wn = warp & 3;
  int g = lane >> 2, cq = lane & 3;
  int m0 = blockIdx.y * 64;
  int n0 = blockIdx.x * 64;

  float acc[2][2][4];
#pragma unroll
  for (int mt = 0; mt < 2; mt++)
#pragma unroll
    for (int nt = 0; nt < 2; nt++)
#pragma unroll
      for (int j = 0; j < 4; j++) acc[mt][nt][j] = 0.f;

  int am = tid >> 2, ak = (tid & 3) * 4;
  int bk0 = tid >> 4, bn0 = (tid & 15) * 4;
  float4 pa, pb;
  pa = *(const float4*)&g_Of[(size_t)(m0 + am)*HID + ak];
  pb = *(const float4*)&Wo[(size_t)bk0*HID + n0 + bn0];

  for (int kb = 0; kb < HID; kb += 16){
    {
      float vv[4] = {pa.x, pa.y, pa.z, pa.w};
      uint32_t hi[4], lo[4];
#pragma unroll
      for (int e = 0; e < 4; e++){
        hi[e] = f2tf32(vv[e]);
        lo[e] = f2tf32(vv[e] - __uint_as_float(hi[e]));
      }
      *(uint4*)&Ah[am][ak] = make_uint4(hi[0], hi[1], hi[2], hi[3]);
      *(uint4*)&Al[am][ak] = make_uint4(lo[0], lo[1], lo[2], lo[3]);
      float wv[4] = {pb.x, pb.y, pb.z, pb.w};
#pragma unroll
      for (int e = 0; e < 4; e++){
        hi[e] = f2tf32(wv[e]);
        lo[e] = f2tf32(wv[e] - __uint_as_float(hi[e]));
      }
      *(uint4*)&Bh[bk0][bn0] = make_uint4(hi[0], hi[1], hi[2], hi[3]);
      *(uint4*)&Bl[bk0][bn0] = make_uint4(lo[0], lo[1], lo[2], lo[3]);
    }
    __syncthreads();
    if (kb + 16 < HID){
      pa = *(const float4*)&g_Of[(size_t)(m0 + am)*HID + kb + 16 + ak];
      pb = *(const float4*)&Wo[(size_t)(kb + 16 + bk0)*HID + n0 + bn0];
    }
#pragma unroll
    for (int ks = 0; ks < 2; ks++){
      int k0 = ks*8 + cq;
      uint32_t ah[2][4], al[2][4];
#pragma unroll
      for (int mt = 0; mt < 2; mt++){
        int mb = wr*32 + mt*16;
        ah[mt][0] = Ah[mb+g][k0];   ah[mt][1] = Ah[mb+g+8][k0];
        ah[mt][2] = Ah[mb+g][k0+4]; ah[mt][3] = Ah[mb+g+8][k0+4];
        al[mt][0] = Al[mb+g][k0];   al[mt][1] = Al[mb+g+8][k0];
        al[mt][2] = Al[mb+g][k0+4]; al[mt][3] = Al[mb+g+8][k0+4];
      }
#pragma unroll
      for (int nt = 0; nt < 2; nt++){
        int nb = wn*16 + nt*8;
        uint32_t bh0 = Bh[k0][nb+g], bh1 = Bh[k0+4][nb+g];
        uint32_t bl0 = Bl[k0][nb+g], bl1 = Bl[k0+4][nb+g];
#pragma unroll
        for (int mt = 0; mt < 2; mt++){
          MMA_TF32(acc[mt][nt], ah[mt][0], ah[mt][1], ah[mt][2], ah[mt][3], bl0, bl1);
          MMA_TF32(acc[mt][nt], al[mt][0], al[mt][1], al[mt][2], al[mt][3], bh0, bh1);
          MMA_TF32(acc[mt][nt], ah[mt][0], ah[mt][1], ah[mt][2], ah[mt][3], bh0, bh1);
        }
      }
    }
    __syncthreads();
  }

#pragma unroll
  for (int mt = 0; mt < 2; mt++){
    int m = m0 + wr*32 + mt*16 + g;
#pragma unroll
    for (int nt = 0; nt < 2; nt++){
      int cc = n0 + wn*16 + nt*8 + cq*2;
      *(float2*)&out[(size_t)m*HID + cc]     = make_float2(acc[mt][nt][0], acc[mt][nt][1]);
      *(float2*)&out[(size_t)(m+8)*HID + cc] = make_float2(acc[mt][nt][2], acc[mt][nt][3]);
    }
  }
}

// ------------------------- launcher -------------------------
extern "C" void kernel_launch(void* const* d_in, const int* in_sizes, int n_in,
                              void* d_out, int out_size){
  const float* x    = (const float*)d_in[0];
  const float* Wq   = (const float*)d_in[1];
  const float* Wk   = (const float*)d_in[2];
  const float* Wv   = (const float*)d_in[3];
  const float* Wa   = (const float*)d_in[4];
  const float* ba   = (const float*)d_in[5];
  const float* Wb   = (const float*)d_in[6];
  const float* bb   = (const float*)d_in[7];
  const float* lpar = (const float*)d_in[8];
  const float* onw  = (const float*)d_in[9];
  const float* Wo   = (const float*)d_in[10];
  float* out = (float*)d_out;

  k_qkv<<<dim3(16, 8, 4), 256>>>(x, Wq, Wk, Wv, Wa, ba, Wb, bb);  // 0 (gates fused)
  k_chunkscan<<<dim3(8, BH), 256>>>();                            // 1
  k_solve<<<dim3(NC, BH), 256>>>(lpar, onw);                      // 2
  k_out<<<dim3(32, 8), 256>>>(Wo, out);                           // 3
}

// round 12
// speedup vs baseline: 1.0304x; 1.0304x over previous
#include <cuda_runtime.h>
#include <math.h>
#include <stdint.h>

#define BN   2
#define TT   256
#define HID  2048
#define NOUT 2048
#define NH   16
#define HD   128
#define BH   32
#define CS   8
#define NC   32
#define NCG  8
#define MROWS (BN*TT)

typedef unsigned long long ull;

// ------------------------- scratch (device globals) -------------------------
__device__ float g_Q[BH*TT*HD];
__device__ float g_K[BH*TT*HD];
__device__ float g_V[BH*TT*HD];
__device__ float g_Of[MROWS*HID];
__device__ float g_g[BH*TT];
__device__ float g_beta[BH*TT];
__device__ float g_Skk[BH*NC*HD*HD];
__device__ float g_Skv[BH*NC*HD*HD];

// ------------------------- helpers -------------------------
__device__ __forceinline__ float warp_sum(float v){
#pragma unroll
  for (int o = 16; o; o >>= 1) v += __shfl_xor_sync(0xffffffffu, v, o);
  return v;
}
__device__ __forceinline__ ull bcast2(float x){
  ull r; asm("mov.b64 %0, {%1, %1};" : "=l"(r) : "f"(x)); return r;
}
__device__ __forceinline__ void ffma2(ull& d, ull a, ull b){
  asm("fma.rn.f32x2 %0, %1, %2, %0;" : "+l"(d) : "l"(a), "l"(b));
}
__device__ __forceinline__ float2 unpack2(ull v){
  float2 f; asm("mov.b64 {%0, %1}, %2;" : "=f"(f.x), "=f"(f.y) : "l"(v)); return f;
}
__device__ __forceinline__ float silu(float z){ return z / (1.f + expf(-z)); }
__device__ __forceinline__ void group_bar(int g){
  asm volatile("bar.sync %0, %1;" :: "r"(1 + g), "r"(128) : "memory");
}
__device__ __forceinline__ uint32_t f2tf32(float v){
  uint32_t r; asm("cvt.rna.tf32.f32 %0, %1;" : "=r"(r) : "f"(v)); return r;
}

#define MMA_TF32(d, a0,a1,a2,a3, b0,b1) \
  asm volatile("mma.sync.aligned.m16n8k8.row.col.f32.tf32.tf32.f32 " \
    "{%0,%1,%2,%3}, {%4,%5,%6,%7}, {%8,%9}, {%0,%1,%2,%3};" \
    : "+f"((d)[0]),"+f"((d)[1]),"+f"((d)[2]),"+f"((d)[3]) \
    : "r"(a0),"r"(a1),"r"(a2),"r"(a3), "r"(b0),"r"(b1))

// ------------------------- K1: QKV GEMM (3xTF32) + SiLU + l2 + fused gates ----
union QkvSmem {
  struct {
    uint32_t Ah[64][20], Al[64][20];
    uint32_t Bh[16][136], Bl[16][136];
    float l2s[64][4];
  } g;
  struct {
    float xr[HID];
    float red[8][32];
  } gate;
};

__global__ void __launch_bounds__(256,2) k_qkv(const float* __restrict__ X,
                                               const float* __restrict__ Wq,
                                               const float* __restrict__ Wk,
                                               const float* __restrict__ Wv,
                                               const float* __restrict__ Wa,
                                               const float* __restrict__ ba,
                                               const float* __restrict__ Wb,
                                               const float* __restrict__ bb){
  int z = blockIdx.z;
  int tid = threadIdx.x;
  __shared__ __align__(16) QkvSmem S;

  if (z == 3){
    // ---- gates path ----
    float* xr = S.gate.xr;
    int cta = blockIdx.y * 16 + blockIdx.x;     // 0..127
    for (int r4 = 0; r4 < 4; r4++){
      int row = cta*4 + r4;
      int b = row >> 8, t = row & 255;
      const float4* xp = (const float4*)(X + (size_t)row * HID);
      for (int idx = tid; idx < HID/4; idx += 256)
        *(float4*)&xr[idx*4] = xp[idx];
      __syncthreads();
      int o = tid & 31, k8 = tid >> 5;
      float partial = 0.f;
      if (o < 16){
        for (int cc = k8*256; cc < k8*256+256; cc++) partial += xr[cc] * Wa[cc*NH + o];
      } else {
        int oo = o - 16;
        for (int cc = k8*256; cc < k8*256+256; cc++) partial += xr[cc] * Wb[cc*NH + oo];
      }
      S.gate.red[k8][o] = partial;
      __syncthreads();
      if (tid < 32){
        float v = 0.f;
#pragma unroll
        for (int u = 0; u < 8; u++) v += S.gate.red[u][tid];
        if (tid < 16){
          float zz = v + ba[tid];
          float ls = (zz >= 0.f) ? -log1pf(expf(-zz)) : (zz - log1pf(expf(zz)));
          g_g[(b*NH + tid)*TT + t] = ls;
        } else {
          int hh = tid - 16;
          float zz = v + bb[hh];
          g_beta[(b*NH + hh)*TT + t] = 1.f / (1.f + expf(-zz));
        }
      }
      __syncthreads();
    }
    return;
  }

  const float* W = z == 0 ? Wq : (z == 1 ? Wk : Wv);
  float* DST     = z == 0 ? g_Q : (z == 1 ? g_K : g_V);

  int lane = tid & 31, warp = tid >> 5;
  int wr = warp >> 2, wn = warp & 3;
  int g = lane >> 2, cq = lane & 3;
  int m0 = blockIdx.y * 64;
  int h = blockIdx.x;
  int n0 = h * 128;

  float acc[2][4][4];
#pragma unroll
  for (int mt = 0; mt < 2; mt++)
#pragma unroll
    for (int nt = 0; nt < 4; nt++)
#pragma unroll
      for (int j = 0; j < 4; j++) acc[mt][nt][j] = 0.f;

  int am = tid >> 2, ak = (tid & 3) * 4;
  int bk0 = tid >> 5, bn0 = (tid & 31) * 4;
  float4 pa, pb[2];
  pa = *(const float4*)&X[(size_t)(m0 + am)*HID + ak];
#pragma unroll
  for (int p = 0; p < 2; p++)
    pb[p] = *(const float4*)&W[(size_t)(bk0 + p*8)*NOUT + n0 + bn0];

  for (int kb = 0; kb < HID; kb += 16){
    {
      float vv[4] = {pa.x, pa.y, pa.z, pa.w};
      uint32_t hi[4], lo[4];
#pragma unroll
      for (int e = 0; e < 4; e++){
        hi[e] = f2tf32(vv[e]);
        lo[e] = f2tf32(vv[e] - __uint_as_float(hi[e]));
      }
      *(uint4*)&S.g.Ah[am][ak] = make_uint4(hi[0], hi[1], hi[2], hi[3]);
      *(uint4*)&S.g.Al[am][ak] = make_uint4(lo[0], lo[1], lo[2], lo[3]);
#pragma unroll
      for (int p = 0; p < 2; p++){
        float wv[4] = {pb[p].x, pb[p].y, pb[p].z, pb[p].w};
#pragma unroll
        for (int e = 0; e < 4; e++){
          hi[e] = f2tf32(wv[e]);
          lo[e] = f2tf32(wv[e] - __uint_as_float(hi[e]));
        }
        *(uint4*)&S.g.Bh[bk0 + p*8][bn0] = make_uint4(hi[0], hi[1], hi[2], hi[3]);
        *(uint4*)&S.g.Bl[bk0 + p*8][bn0] = make_uint4(lo[0], lo[1], lo[2], lo[3]);
      }
    }
    __syncthreads();
    if (kb + 16 < HID){
      pa = *(const float4*)&X[(size_t)(m0 + am)*HID + kb + 16 + ak];
#pragma unroll
      for (int p = 0; p < 2; p++)
        pb[p] = *(const float4*)&W[(size_t)(kb + 16 + bk0 + p*8)*NOUT + n0 + bn0];
    }
#pragma unroll
    for (int ks = 0; ks < 2; ks++){
      int k0 = ks*8 + cq;
      uint32_t ah[2][4], al[2][4];
#pragma unroll
      for (int mt = 0; mt < 2; mt++){
        int mb = wr*32 + mt*16;
        ah[mt][0] = S.g.Ah[mb+g][k0];   ah[mt][1] = S.g.Ah[mb+g+8][k0];
        ah[mt][2] = S.g.Ah[mb+g][k0+4]; ah[mt][3] = S.g.Ah[mb+g+8][k0+4];
        al[mt][0] = S.g.Al[mb+g][k0];   al[mt][1] = S.g.Al[mb+g+8][k0];
        al[mt][2] = S.g.Al[mb+g][k0+4]; al[mt][3] = S.g.Al[mb+g+8][k0+4];
      }
#pragma unroll
      for (int nt = 0; nt < 4; nt++){
        int nb = wn*32 + nt*8;
        uint32_t bh0 = S.g.Bh[k0][nb+g], bh1 = S.g.Bh[k0+4][nb+g];
        uint32_t bl0 = S.g.Bl[k0][nb+g], bl1 = S.g.Bl[k0+4][nb+g];
#pragma unroll
        for (int mt = 0; mt < 2; mt++){
          MMA_TF32(acc[mt][nt], ah[mt][0], ah[mt][1], ah[mt][2], ah[mt][3], bl0, bl1);
          MMA_TF32(acc[mt][nt], al[mt][0], al[mt][1], al[mt][2], al[mt][3], bh0, bh1);
          MMA_TF32(acc[mt][nt], ah[mt][0], ah[mt][1], ah[mt][2], ah[mt][3], bh0, bh1);
        }
      }
    }
    __syncthreads();
  }

  float v[2][4][4];
#pragma unroll
  for (int mt = 0; mt < 2; mt++)
#pragma unroll
    for (int nt = 0; nt < 4; nt++)
#pragma unroll
      for (int j = 0; j < 4; j++) v[mt][nt][j] = silu(acc[mt][nt][j]);

  float scale[2][2] = {{1.f,1.f},{1.f,1.f}};
  if (z < 2){
#pragma unroll
    for (int mt = 0; mt < 2; mt++){
      float s0 = 0.f, s1 = 0.f;
#pragma unroll
      for (int nt = 0; nt < 4; nt++){
        s0 += v[mt][nt][0]*v[mt][nt][0] + v[mt][nt][1]*v[mt][nt][1];
        s1 += v[mt][nt][2]*v[mt][nt][2] + v[mt][nt][3]*v[mt][nt][3];
      }
      s0 += __shfl_xor_sync(0xffffffffu, s0, 1);
      s0 += __shfl_xor_sync(0xffffffffu, s0, 2);
      s1 += __shfl_xor_sync(0xffffffffu, s1, 1);
      s1 += __shfl_xor_sync(0xffffffffu, s1, 2);
      if (cq == 0){
        S.g.l2s[wr*32 + mt*16 + g][wn]     = s0;
        S.g.l2s[wr*32 + mt*16 + g + 8][wn] = s1;
      }
    }
    __syncthreads();
#pragma unroll
    for (int mt = 0; mt < 2; mt++){
      float4 q0 = *(const float4*)&S.g.l2s[wr*32 + mt*16 + g][0];
      float4 q1 = *(const float4*)&S.g.l2s[wr*32 + mt*16 + g + 8][0];
      float s0 = (q0.x + q0.y) + (q0.z + q0.w);
      float s1 = (q1.x + q1.y) + (q1.z + q1.w);
      scale[mt][0] = 1.f / fmaxf(sqrtf(s0), 1e-12f);
      scale[mt][1] = 1.f / fmaxf(sqrtf(s1), 1e-12f);
    }
  }

#pragma unroll
  for (int mt = 0; mt < 2; mt++){
    int m = m0 + wr*32 + mt*16 + g;
    int b = m >> 8, t = m & 255;
#pragma unroll
    for (int nt = 0; nt < 4; nt++){
      int d = wn*32 + nt*8 + cq*2;
      size_t off = ((size_t)((b*NH + h)*TT + t))*HD + d;
      *(float2*)&DST[off] = make_float2(v[mt][nt][0]*scale[mt][0],
                                        v[mt][nt][1]*scale[mt][0]);
      *(float2*)&DST[off + 8*HD] = make_float2(v[mt][nt][2]*scale[mt][1],
                                               v[mt][nt][3]*scale[mt][1]);
    }
  }
}

// ------------------------- K2: chunk sums + scan fused ------------------------
__global__ void __launch_bounds__(256,4) k_chunkscan(){
  int vslab = blockIdx.x, bh = blockIdx.y;
  int tid = threadIdx.x;
  int i  = vslab*16 + (tid >> 4);
  int j0 = (tid & 15) * 8;
  __shared__ __align__(16) float ks[CS][HD], vs[CS][HD];
  __shared__ float coef[CS];
  __shared__ float dcs;
  float ckk[8], ckv[8];
#pragma unroll
  for (int u = 0; u < 8; u++){ ckk[u] = 0.f; ckv[u] = 0.f; }

  for (int c = 0; c < NC; c++){
    if (c) __syncthreads();
    {
      const float4* Kp = (const float4*)(g_K + (size_t)(bh*TT + c*CS)*HD);
      const float4* Vp = (const float4*)(g_V + (size_t)(bh*TT + c*CS)*HD);
      ((float4*)ks)[tid] = Kp[tid];
      ((float4*)vs)[tid] = Vp[tid];
    }
    if (tid < CS){
      float s = 0.f;
      for (int u = tid + 1; u < CS; u++) s += g_g[bh*TT + c*CS + u];
      coef[tid] = g_beta[bh*TT + c*CS + tid] * expf(s);
    }
    if (tid == 8){
      float s = 0.f;
      for (int u = 0; u < CS; u++) s += g_g[bh*TT + c*CS + u];
      dcs = expf(s);
    }
    __syncthreads();
    float dc = dcs;
#pragma unroll
    for (int u = 0; u < 8; u++){ ckk[u] *= dc; ckv[u] *= dc; }
#pragma unroll
    for (int s = 0; s < CS; s++){
      float ki = ks[s][i] * coef[s];
      float4 ka = *(const float4*)&ks[s][j0];
      float4 kb = *(const float4*)&ks[s][j0+4];
      float4 va = *(const float4*)&vs[s][j0];
      float4 vb = *(const float4*)&vs[s][j0+4];
      ckk[0] += ki*ka.x; ckk[1] += ki*ka.y; ckk[2] += ki*ka.z; ckk[3] += ki*ka.w;
      ckk[4] += ki*kb.x; ckk[5] += ki*kb.y; ckk[6] += ki*kb.z; ckk[7] += ki*kb.w;
      ckv[0] += ki*va.x; ckv[1] += ki*va.y; ckv[2] += ki*va.z; ckv[3] += ki*va.w;
      ckv[4] += ki*vb.x; ckv[5] += ki*vb.y; ckv[6] += ki*vb.z; ckv[7] += ki*vb.w;
    }
    size_t base = ((size_t)(bh*NC + c) << 14) + (size_t)i*HD + j0;
    *(float4*)&g_Skk[base]   = make_float4(ckk[0], ckk[1], ckk[2], ckk[3]);
    *(float4*)&g_Skk[base+4] = make_float4(ckk[4], ckk[5], ckk[6], ckk[7]);
    *(float4*)&g_Skv[base]   = make_float4(ckv[0], ckv[1], ckv[2], ckv[3]);
    *(float4*)&g_Skv[base+4] = make_float4(ckv[4], ckv[5], ckv[6], ckv[7]);
  }
}

// ------------------------- K3: batched 8-RHS CG solve (256 thr, 2 CTAs/SM) ----
#define PHASE_A(MSM) do { \
  ull y0a=0ull, y0b=0ull, y0c=0ull, y0d=0ull; \
  ull y1a=0ull, y1b=0ull, y1c=0ull, y1d=0ull; \
  _Pragma("unroll") \
  for (int jj = 0; jj < 32; jj++){ \
    ulonglong2 pA = *(const ulonglong2*)&P[mq*32+jj][0]; \
    ulonglong2 pB = *(const ulonglong2*)&P[mq*32+jj][4]; \
    ull h0 = bcast2(hk[jj]); \
    ull h1 = bcast2(hk[32+jj]); \
    ffma2(y0a, h0, pA.x); ffma2(y0b, h0, pA.y); ffma2(y0c, h0, pB.x); ffma2(y0d, h0, pB.y); \
    ffma2(y1a, h1, pA.x); ffma2(y1b, h1, pA.y); ffma2(y1c, h1, pB.x); ffma2(y1d, h1, pB.y); \
  } \
  *(ulonglong2*)&part[mq][mi][0] = make_ulonglong2(y0a, y0b); \
  *(ulonglong2*)&part[mq][mi][4] = make_ulonglong2(y0c, y0d); \
  *(ulonglong2*)&part[mq][mi+64][0] = make_ulonglong2(y1a, y1b); \
  *(ulonglong2*)&part[mq][mi+64][4] = make_ulonglong2(y1c, y1d); \
  { float4 kv_ = *(const float4*)&MSM[warp][lane*4]; \
    _Pragma("unroll") \
    for (int t_ = 0; t_ < 8; t_++){ \
      float4 pv_ = *(const float4*)&PT[t_][lane*4]; \
      float pd_ = kv_.x*pv_.x + kv_.y*pv_.y + kv_.z*pv_.z + kv_.w*pv_.w; \
      pd_ = warp_sum(pd_); \
      if (lane == 0) dots[t_][warp] = pd_; \
    } } \
} while(0)

#define ASM4(OUT) do { \
  float4 ya_ = make_float4(0.f, 0.f, 0.f, 0.f); \
  _Pragma("unroll") \
  for (int q2 = 0; q2 < 4; q2++){ \
    float4 pr_ = *(const float4*)&part[q2][si][t0]; \
    ya_.x += pr_.x; ya_.y += pr_.y; ya_.z += pr_.z; ya_.w += pr_.w; \
  } \
  float yarr_[4] = {ya_.x, ya_.y, ya_.z, ya_.w}; \
  _Pragma("unroll") \
  for (int u = 0; u < 4; u++){ \
    int t_ = t0 + u; \
    float a_ = cdec[t_] * yarr_[u]; \
    float4 d0_ = *(const float4*)&dots[t_][0]; \
    float4 d1_ = *(const float4*)&dots[t_][4]; \
    float4 w0_ = *(const float4*)&Wc[t_][0]; \
    float4 w1_ = *(const float4*)&Wc[t_][4]; \
    a_ += (w0_.x*d0_.x)*ksi[0] + (w0_.y*d0_.y)*ksi[1] \
        + (w0_.z*d0_.z)*ksi[2] + (w0_.w*d0_.w)*ksi[3] \
        + (w1_.x*d1_.x)*ksi[4] + (w1_.y*d1_.y)*ksi[5] \
        + (w1_.z*d1_.z)*ksi[6] + (w1_.w*d1_.w)*ksi[7]; \
    OUT[u] = a_; \
  } \
} while(0)

__global__ void __launch_bounds__(256,2) k_solve(const float* __restrict__ lp,
                                                 const float* __restrict__ onw){
  int c = blockIdx.x, bh = blockIdx.y;
  int b = bh >> 4, h = bh & 15;
  int tid = threadIdx.x;
  int si = tid & 127, sg2 = tid >> 7, lane = tid & 31, warp = tid >> 5;
  int mi = tid & 63, mq = tid >> 6;
  int g0 = bh*TT + c*CS;
  int t0 = sg2*4;

  __shared__ __align__(16) float Ksm[CS][HD], Vsm[CS][HD], Qsm[CS][HD];
  __shared__ __align__(16) float P[HD][12];
  __shared__ __align__(16) float PT[CS][HD+4];
  __shared__ __align__(16) float part[4][HD][12];
  __shared__ __align__(16) float dots[CS][CS];
  __shared__ __align__(16) float Wc[CS][CS];
  __shared__ float cdec[CS];
  __shared__ float lam[HD], dg[HD], gsm[CS], bsm[CS];
  __shared__ __align__(16) float wredA[4][8];
  __shared__ __align__(16) float wredB[4][8];

  {
    const float4* Kp = (const float4*)(g_K + (size_t)g0*HD);
    const float4* Vp = (const float4*)(g_V + (size_t)g0*HD);
    const float4* Qp = (const float4*)(g_Q + (size_t)g0*HD);
    ((float4*)Ksm)[tid] = Kp[tid];
    ((float4*)Qsm)[tid] = Qp[tid];
    ((float4*)Vsm)[tid] = Vp[tid];
  }
  if (tid >= 128 && tid < 136){ gsm[tid-128] = g_g[g0 + tid-128]; bsm[tid-128] = g_beta[g0 + tid-128]; }
  if (tid < 128){
    float zz = lp[h*HD + tid];
    float sp = (zz > 20.f) ? zz : log1pf(expf(zz));
    lam[tid] = sp + 0.25f;
  }
  float hk[64];
  if (c == 0){
#pragma unroll
    for (int jj = 0; jj < 64; jj++) hk[jj] = 0.f;
  } else {
    size_t base = ((size_t)(bh*NC + (c-1)) << 14) + mq*32;
#pragma unroll
    for (int jj = 0; jj < 32; jj += 4){
      float4 a = *(const float4*)&g_Skk[base + (size_t)mi*HD + jj];
      hk[jj] = a.x; hk[jj+1] = a.y; hk[jj+2] = a.z; hk[jj+3] = a.w;
      float4 a2 = *(const float4*)&g_Skk[base + (size_t)(mi+64)*HD + jj];
      hk[32+jj] = a2.x; hk[33+jj] = a2.y; hk[34+jj] = a2.z; hk[35+jj] = a2.w;
    }
  }
  if (mq == (mi >> 5))       dg[mi]      = hk[mi & 31];
  if (mq == 2 + (mi >> 5))   dg[mi + 64] = hk[32 + (mi & 31)];
  __syncthreads();

  if (tid < 64){
    int t_ = tid >> 3, s_ = tid & 7;
    float w = 0.f;
    if (s_ <= t_){
      float s = 0.f;
      for (int u = s_+1; u <= t_; u++) s += gsm[u];
      w = bsm[s_] * expf(s);
    }
    Wc[t_][s_] = w;
  }
  if (tid >= 64 && tid < 72){
    int t_ = tid - 64;
    float s = 0.f;
    for (int u = 0; u <= t_; u++) s += gsm[u];
    cdec[t_] = expf(s);
  }
  __syncthreads();

  float ksi[CS];
#pragma unroll
  for (int s = 0; s < CS; s++) ksi[s] = Ksm[s][si];
  float xv[4], rv[4], pv[4], dloc[4], qv[4];
  unsigned dmask = 0;
#pragma unroll
  for (int u = 0; u < 4; u++){
    int t = t0 + u;
    float diag = cdec[t]*dg[si] + lam[si];
#pragma unroll
    for (int s = 0; s < CS; s++) diag += Wc[t][s] * ksi[s] * ksi[s];
    float x = Qsm[t][si] / (diag + 1e-8f);
    xv[u] = x; P[si][t] = x; PT[t][si] = x;
  }
  __syncthreads();

  PHASE_A(Ksm);
  __syncthreads();
  {
    float av[4];
    ASM4(av);
#pragma unroll
    for (int u = 0; u < 4; u++){
      int t = t0 + u;
      float r = Qsm[t][si] - (av[u] + lam[si]*xv[u]);
      rv[u] = r; pv[u] = r;
      float rr = warp_sum(r*r);
      if (lane == 0) wredA[u][warp] = rr;
      P[si][t] = r; PT[t][si] = r;
    }
  }
  group_bar(sg2);
#pragma unroll
  for (int u = 0; u < 4; u++){
    float4 wv = *(const float4*)&wredA[u][sg2*4];
    dloc[u] = (wv.x + wv.y) + (wv.z + wv.w);
  }
  __syncthreads();

  for (int it = 0; it < NCG; it++){
    PHASE_A(Ksm);
    __syncthreads();
    {
      ASM4(qv);
#pragma unroll
      for (int u = 0; u < 4; u++){
        qv[u] += lam[si] * pv[u];
        float pq = warp_sum(pv[u] * qv[u]);
        if (lane == 0) wredA[u][warp] = pq;
      }
    }
    group_bar(sg2);
#pragma unroll
    for (int u = 0; u < 4; u++){
      float4 wv = *(const float4*)&wredA[u][sg2*4];
      float pq = (wv.x + wv.y) + (wv.z + wv.w);
      if (dloc[u] < 1e-10f) dmask |= 1u << u;
      if (fabsf(pq) < 1e-10f) dmask |= 1u << u;
      float alpha = (dmask >> u & 1u) ? 0.f : dloc[u] / pq;
      xv[u] += alpha * pv[u];
      rv[u] -= alpha * qv[u];
      float rr = warp_sum(rv[u] * rv[u]);
      if (lane == 0) wredB[u][warp] = rr;
    }
    group_bar(sg2);
#pragma unroll
    for (int u = 0; u < 4; u++){
      int t = t0 + u;
      float4 wv = *(const float4*)&wredB[u][sg2*4];
      float dn = (wv.x + wv.y) + (wv.z + wv.w);
      if (!(dmask >> u & 1u)){
        float bet = dn / dloc[u];
        dloc[u] = dn;
        pv[u] = rv[u] + bet * pv[u];
      }
      P[si][t] = pv[u]; PT[t][si] = pv[u];
    }
    __syncthreads();
  }

#pragma unroll
  for (int u = 0; u < 4; u++){
    int t = t0 + u;
    P[si][t] = xv[u]; PT[t][si] = xv[u];
  }
  if (c == 0){
#pragma unroll
    for (int jj = 0; jj < 64; jj++) hk[jj] = 0.f;
  } else {
    size_t base = ((size_t)(bh*NC + (c-1)) << 14) + mq*32;
#pragma unroll
    for (int jj = 0; jj < 32; jj += 4){
      float4 a = *(const float4*)&g_Skv[base + (size_t)mi*HD + jj];
      hk[jj] = a.x; hk[jj+1] = a.y; hk[jj+2] = a.z; hk[jj+3] = a.w;
      float4 a2 = *(const float4*)&g_Skv[base + (size_t)(mi+64)*HD + jj];
      hk[32+jj] = a2.x; hk[33+jj] = a2.y; hk[34+jj] = a2.z; hk[35+jj] = a2.w;
    }
  }
  __syncthreads();
  PHASE_A(Vsm);
  __syncthreads();
  float ov[4];
  ASM4(ov);
#pragma unroll
  for (int u = 0; u < 4; u++){
    float ss = warp_sum(ov[u]*ov[u]);
    if (lane == 0) wredA[u][warp] = ss;
  }
  group_bar(sg2);
  float wnv = onw[si];
#pragma unroll
  for (int u = 0; u < 4; u++){
    int t = t0 + u;
    float4 wv = *(const float4*)&wredA[u][sg2*4];
    float ms = ((wv.x + wv.y) + (wv.z + wv.w)) * (1.f/128.f);
    float rms = sqrtf(ms + 1e-6f);
    int ts = c*CS + t;
    g_Of[(size_t)(b*TT + ts)*HID + h*HD + si] = ov[u] / rms * wnv;
  }
}

// ------------------------- K4: output projection (3xTF32, split-K=2) ----------
// 64x128 tile; blockIdx.z = K-half; partials combined via atomicAdd
// (exactly 2 contributions per element -> fp32 add commutative -> deterministic).
__global__ void __launch_bounds__(256,2) k_out(const float* __restrict__ Wo,
                                               float* __restrict__ out){
  __shared__ __align__(16) uint32_t Ah[64][20], Al[64][20];
  __shared__ __align__(16) uint32_t Bh[16][136], Bl[16][136];

  int tid = threadIdx.x;
  int lane = tid & 31, warp = tid >> 5;
  int wr = warp >> 2, wn = warp & 3;
  int g = lane >> 2, cq = lane & 3;
  int m0 = blockIdx.y * 64;
  int n0 = blockIdx.x * 128;
  int kbase = blockIdx.z * (HID/2);     // 0 or 1024

  float acc[2][4][4];
#pragma unroll
  for (int mt = 0; mt < 2; mt++)
#pragma unroll
    for (int nt = 0; nt < 4; nt++)
#pragma unroll
      for (int j = 0; j < 4; j++) acc[mt][nt][j] = 0.f;

  int am = tid >> 2, ak = (tid & 3) * 4;
  int bk0 = tid >> 5, bn0 = (tid & 31) * 4;
  float4 pa, pb[2];
  pa = *(const float4*)&g_Of[(size_t)(m0 + am)*HID + kbase + ak];
#pragma unroll
  for (int p = 0; p < 2; p++)
    pb[p] = *(const float4*)&Wo[(size_t)(kbase + bk0 + p*8)*HID + n0 + bn0];

  for (int kb = 0; kb < HID/2; kb += 16){
    {
      float vv[4] = {pa.x, pa.y, pa.z, pa.w};
      uint32_t hi[4], lo[4];
#pragma unroll
      for (int e = 0; e < 4; e++){
        hi[e] = f2tf32(vv[e]);
        lo[e] = f2tf32(vv[e] - __uint_as_float(hi[e]));
      }
      *(uint4*)&Ah[am][ak] = make_uint4(hi[0], hi[1], hi[2], hi[3]);
      *(uint4*)&Al[am][ak] = make_uint4(lo[0], lo[1], lo[2], lo[3]);
#pragma unroll
      for (int p = 0; p < 2; p++){
        float wv[4] = {pb[p].x, pb[p].y, pb[p].z, pb[p].w};
#pragma unroll
        for (int e = 0; e < 4; e++){
          hi[e] = f2tf32(wv[e]);
          lo[e] = f2tf32(wv[e] - __uint_as_float(hi[e]));
        }
        *(uint4*)&Bh[bk0 + p*8][bn0] = make_uint4(hi[0], hi[1], hi[2], hi[3]);
        *(uint4*)&Bl[bk0 + p*8][bn0] = make_uint4(lo[0], lo[1], lo[2], lo[3]);
      }
    }
    __syncthreads();
    if (kb + 16 < HID/2){
      pa = *(const float4*)&g_Of[(size_t)(m0 + am)*HID + kbase + kb + 16 + ak];
#pragma unroll
      for (int p = 0; p < 2; p++)
        pb[p] = *(const float4*)&Wo[(size_t)(kbase + kb + 16 + bk0 + p*8)*HID + n0 + bn0];
    }
#pragma unroll
    for (int ks = 0; ks < 2; ks++){
      int k0 = ks*8 + cq;
      uint32_t ah[2][4], al[2][4];
#pragma unroll
      for (int mt = 0; mt < 2; mt++){
        int mb = wr*32 + mt*16;
        ah[mt][0] = Ah[mb+g][k0];   ah[mt][1] = Ah[mb+g+8][k0];
        ah[mt][2] = Ah[mb+g][k0+4]; ah[mt][3] = Ah[mb+g+8][k0+4];
        al[mt][0] = Al[mb+g][k0];   al[mt][1] = Al[mb+g+8][k0];
        al[mt][2] = Al[mb+g][k0+4]; al[mt][3] = Al[mb+g+8][k0+4];
      }
#pragma unroll
      for (int nt = 0; nt < 4; nt++){
        int nb = wn*32 + nt*8;
        uint32_t bh0 = Bh[k0][nb+g], bh1 = Bh[k0+4][nb+g];
        uint32_t bl0 = Bl[k0][nb+g], bl1 = Bl[k0+4][nb+g];
#pragma unroll
        for (int mt = 0; mt < 2; mt++){
          MMA_TF32(acc[mt][nt], ah[mt][0], ah[mt][1], ah[mt][2], ah[mt][3], bl0, bl1);
          MMA_TF32(acc[mt][nt], al[mt][0], al[mt][1], al[mt][2], al[mt][3], bh0, bh1);
          MMA_TF32(acc[mt][nt], ah[mt][0], ah[mt][1], ah[mt][2], ah[mt][3], bh0, bh1);
        }
      }
    }
    __syncthreads();
  }

#pragma unroll
  for (int mt = 0; mt < 2; mt++){
    int m = m0 + wr*32 + mt*16 + g;
#pragma unroll
    for (int nt = 0; nt < 4; nt++){
      int cc = n0 + wn*32 + nt*8 + cq*2;
      atomicAdd(&out[(size_t)m*HID + cc],       acc[mt][nt][0]);
      atomicAdd(&out[(size_t)m*HID + cc + 1],   acc[mt][nt][1]);
      atomicAdd(&out[(size_t)(m+8)*HID + cc],   acc[mt][nt][2]);
      atomicAdd(&out[(size_t)(m+8)*HID + cc+1], acc[mt][nt][3]);
    }
  }
}

// ------------------------- launcher -------------------------
extern "C" void kernel_launch(void* const* d_in, const int* in_sizes, int n_in,
                              void* d_out, int out_size){
  const float* x    = (const float*)d_in[0];
  const float* Wq   = (const float*)d_in[1];
  const float* Wk   = (const float*)d_in[2];
  const float* Wv   = (const float*)d_in[3];
  const float* Wa   = (const float*)d_in[4];
  const float* ba   = (const float*)d_in[5];
  const float* Wb   = (const float*)d_in[6];
  const float* bb   = (const float*)d_in[7];
  const float* lpar = (const float*)d_in[8];
  const float* onw  = (const float*)d_in[9];
  const float* Wo   = (const float*)d_in[10];
  float* out = (float*)d_out;

  k_qkv<<<dim3(16, 8, 4), 256>>>(x, Wq, Wk, Wv, Wa, ba, Wb, bb);  // gates fused
  k_chunkscan<<<dim3(8, BH), 256>>>();
  k_solve<<<dim3(NC, BH), 256>>>(lpar, onw);
  cudaMemsetAsync(out, 0, (size_t)out_size * sizeof(float));
  k_out<<<dim3(16, 8, 2), 256>>>(Wo, out);
}

// round 13
// speedup vs baseline: 1.0390x; 1.0084x over previous
#include <cuda_runtime.h>
#include <math.h>
#include <stdint.h>

#define BN   2
#define TT   256
#define HID  2048
#define NOUT 2048
#define NH   16
#define HD   128
#define BH   32
#define CS   8
#define NC   32
#define NCG  7
#define MROWS (BN*TT)

typedef unsigned long long ull;

// ------------------------- scratch (device globals) -------------------------
__device__ float g_Q[BH*TT*HD];
__device__ float g_K[BH*TT*HD];
__device__ float g_V[BH*TT*HD];
__device__ float g_Of[MROWS*HID];
__device__ float g_g[BH*TT];
__device__ float g_beta[BH*TT];
__device__ float g_Skk[BH*NC*HD*HD];
__device__ float g_Skv[BH*NC*HD*HD];

// ------------------------- helpers -------------------------
__device__ __forceinline__ float warp_sum(float v){
#pragma unroll
  for (int o = 16; o; o >>= 1) v += __shfl_xor_sync(0xffffffffu, v, o);
  return v;
}
__device__ __forceinline__ ull bcast2(float x){
  ull r; asm("mov.b64 %0, {%1, %1};" : "=l"(r) : "f"(x)); return r;
}
__device__ __forceinline__ void ffma2(ull& d, ull a, ull b){
  asm("fma.rn.f32x2 %0, %1, %2, %0;" : "+l"(d) : "l"(a), "l"(b));
}
__device__ __forceinline__ float2 unpack2(ull v){
  float2 f; asm("mov.b64 {%0, %1}, %2;" : "=f"(f.x), "=f"(f.y) : "l"(v)); return f;
}
__device__ __forceinline__ float silu(float z){ return z / (1.f + expf(-z)); }
__device__ __forceinline__ void group_bar(int g){
  asm volatile("bar.sync %0, %1;" :: "r"(1 + g), "r"(128) : "memory");
}
__device__ __forceinline__ uint32_t f2tf32(float v){
  uint32_t r; asm("cvt.rna.tf32.f32 %0, %1;" : "=r"(r) : "f"(v)); return r;
}

#define MMA_TF32(d, a0,a1,a2,a3, b0,b1) \
  asm volatile("mma.sync.aligned.m16n8k8.row.col.f32.tf32.tf32.f32 " \
    "{%0,%1,%2,%3}, {%4,%5,%6,%7}, {%8,%9}, {%0,%1,%2,%3};" \
    : "+f"((d)[0]),"+f"((d)[1]),"+f"((d)[2]),"+f"((d)[3]) \
    : "r"(a0),"r"(a1),"r"(a2),"r"(a3), "r"(b0),"r"(b1))

// ------------------------- K1: QKV GEMM (3xTF32) + SiLU + l2 + fused gates ----
union QkvSmem {
  struct {
    uint32_t Ah[64][20], Al[64][20];
    uint32_t Bh[16][136], Bl[16][136];
    float l2s[64][4];
  } g;
  struct {
    float xr[HID];
    float red[8][32];
  } gate;
};

__global__ void __launch_bounds__(256,2) k_qkv(const float* __restrict__ X,
                                               const float* __restrict__ Wq,
                                               const float* __restrict__ Wk,
                                               const float* __restrict__ Wv,
                                               const float* __restrict__ Wa,
                                               const float* __restrict__ ba,
                                               const float* __restrict__ Wb,
                                               const float* __restrict__ bb){
  int z = blockIdx.z;
  int tid = threadIdx.x;
  __shared__ __align__(16) QkvSmem S;

  if (z == 3){
    // ---- gates path ----
    float* xr = S.gate.xr;
    int cta = blockIdx.y * 16 + blockIdx.x;     // 0..127
    for (int r4 = 0; r4 < 4; r4++){
      int row = cta*4 + r4;
      int b = row >> 8, t = row & 255;
      const float4* xp = (const float4*)(X + (size_t)row * HID);
      for (int idx = tid; idx < HID/4; idx += 256)
        *(float4*)&xr[idx*4] = xp[idx];
      __syncthreads();
      int o = tid & 31, k8 = tid >> 5;
      float partial = 0.f;
      if (o < 16){
        for (int cc = k8*256; cc < k8*256+256; cc++) partial += xr[cc] * Wa[cc*NH + o];
      } else {
        int oo = o - 16;
        for (int cc = k8*256; cc < k8*256+256; cc++) partial += xr[cc] * Wb[cc*NH + oo];
      }
      S.gate.red[k8][o] = partial;
      __syncthreads();
      if (tid < 32){
        float v = 0.f;
#pragma unroll
        for (int u = 0; u < 8; u++) v += S.gate.red[u][tid];
        if (tid < 16){
          float zz = v + ba[tid];
          float ls = (zz >= 0.f) ? -log1pf(expf(-zz)) : (zz - log1pf(expf(zz)));
          g_g[(b*NH + tid)*TT + t] = ls;
        } else {
          int hh = tid - 16;
          float zz = v + bb[hh];
          g_beta[(b*NH + hh)*TT + t] = 1.f / (1.f + expf(-zz));
        }
      }
      __syncthreads();
    }
    return;
  }

  const float* W = z == 0 ? Wq : (z == 1 ? Wk : Wv);
  float* DST     = z == 0 ? g_Q : (z == 1 ? g_K : g_V);

  int lane = tid & 31, warp = tid >> 5;
  int wr = warp >> 2, wn = warp & 3;
  int g = lane >> 2, cq = lane & 3;
  int m0 = blockIdx.y * 64;
  int h = blockIdx.x;
  int n0 = h * 128;

  float acc[2][4][4];
#pragma unroll
  for (int mt = 0; mt < 2; mt++)
#pragma unroll
    for (int nt = 0; nt < 4; nt++)
#pragma unroll
      for (int j = 0; j < 4; j++) acc[mt][nt][j] = 0.f;

  int am = tid >> 2, ak = (tid & 3) * 4;
  int bk0 = tid >> 5, bn0 = (tid & 31) * 4;
  float4 pa, pb[2];
  pa = *(const float4*)&X[(size_t)(m0 + am)*HID + ak];
#pragma unroll
  for (int p = 0; p < 2; p++)
    pb[p] = *(const float4*)&W[(size_t)(bk0 + p*8)*NOUT + n0 + bn0];

  for (int kb = 0; kb < HID; kb += 16){
    {
      float vv[4] = {pa.x, pa.y, pa.z, pa.w};
      uint32_t hi[4], lo[4];
#pragma unroll
      for (int e = 0; e < 4; e++){
        hi[e] = f2tf32(vv[e]);
        lo[e] = f2tf32(vv[e] - __uint_as_float(hi[e]));
      }
      *(uint4*)&S.g.Ah[am][ak] = make_uint4(hi[0], hi[1], hi[2], hi[3]);
      *(uint4*)&S.g.Al[am][ak] = make_uint4(lo[0], lo[1], lo[2], lo[3]);
#pragma unroll
      for (int p = 0; p < 2; p++){
        float wv[4] = {pb[p].x, pb[p].y, pb[p].z, pb[p].w};
#pragma unroll
        for (int e = 0; e < 4; e++){
          hi[e] = f2tf32(wv[e]);
          lo[e] = f2tf32(wv[e] - __uint_as_float(hi[e]));
        }
        *(uint4*)&S.g.Bh[bk0 + p*8][bn0] = make_uint4(hi[0], hi[1], hi[2], hi[3]);
        *(uint4*)&S.g.Bl[bk0 + p*8][bn0] = make_uint4(lo[0], lo[1], lo[2], lo[3]);
      }
    }
    __syncthreads();
    if (kb + 16 < HID){
      pa = *(const float4*)&X[(size_t)(m0 + am)*HID + kb + 16 + ak];
#pragma unroll
      for (int p = 0; p < 2; p++)
        pb[p] = *(const float4*)&W[(size_t)(kb + 16 + bk0 + p*8)*NOUT + n0 + bn0];
    }
#pragma unroll
    for (int ks = 0; ks < 2; ks++){
      int k0 = ks*8 + cq;
      uint32_t ah[2][4], al[2][4];
#pragma unroll
      for (int mt = 0; mt < 2; mt++){
        int mb = wr*32 + mt*16;
        ah[mt][0] = S.g.Ah[mb+g][k0];   ah[mt][1] = S.g.Ah[mb+g+8][k0];
        ah[mt][2] = S.g.Ah[mb+g][k0+4]; ah[mt][3] = S.g.Ah[mb+g+8][k0+4];
        al[mt][0] = S.g.Al[mb+g][k0];   al[mt][1] = S.g.Al[mb+g+8][k0];
        al[mt][2] = S.g.Al[mb+g][k0+4]; al[mt][3] = S.g.Al[mb+g+8][k0+4];
      }
#pragma unroll
      for (int nt = 0; nt < 4; nt++){
        int nb = wn*32 + nt*8;
        uint32_t bh0 = S.g.Bh[k0][nb+g], bh1 = S.g.Bh[k0+4][nb+g];
        uint32_t bl0 = S.g.Bl[k0][nb+g], bl1 = S.g.Bl[k0+4][nb+g];
#pragma unroll
        for (int mt = 0; mt < 2; mt++){
          MMA_TF32(acc[mt][nt], ah[mt][0], ah[mt][1], ah[mt][2], ah[mt][3], bl0, bl1);
          MMA_TF32(acc[mt][nt], al[mt][0], al[mt][1], al[mt][2], al[mt][3], bh0, bh1);
          MMA_TF32(acc[mt][nt], ah[mt][0], ah[mt][1], ah[mt][2], ah[mt][3], bh0, bh1);
        }
      }
    }
    __syncthreads();
  }

  float v[2][4][4];
#pragma unroll
  for (int mt = 0; mt < 2; mt++)
#pragma unroll
    for (int nt = 0; nt < 4; nt++)
#pragma unroll
      for (int j = 0; j < 4; j++) v[mt][nt][j] = silu(acc[mt][nt][j]);

  float scale[2][2] = {{1.f,1.f},{1.f,1.f}};
  if (z < 2){
#pragma unroll
    for (int mt = 0; mt < 2; mt++){
      float s0 = 0.f, s1 = 0.f;
#pragma unroll
      for (int nt = 0; nt < 4; nt++){
        s0 += v[mt][nt][0]*v[mt][nt][0] + v[mt][nt][1]*v[mt][nt][1];
        s1 += v[mt][nt][2]*v[mt][nt][2] + v[mt][nt][3]*v[mt][nt][3];
      }
      s0 += __shfl_xor_sync(0xffffffffu, s0, 1);
      s0 += __shfl_xor_sync(0xffffffffu, s0, 2);
      s1 += __shfl_xor_sync(0xffffffffu, s1, 1);
      s1 += __shfl_xor_sync(0xffffffffu, s1, 2);
      if (cq == 0){
        S.g.l2s[wr*32 + mt*16 + g][wn]     = s0;
        S.g.l2s[wr*32 + mt*16 + g + 8][wn] = s1;
      }
    }
    __syncthreads();
#pragma unroll
    for (int mt = 0; mt < 2; mt++){
      float4 q0 = *(const float4*)&S.g.l2s[wr*32 + mt*16 + g][0];
      float4 q1 = *(const float4*)&S.g.l2s[wr*32 + mt*16 + g + 8][0];
      float s0 = (q0.x + q0.y) + (q0.z + q0.w);
      float s1 = (q1.x + q1.y) + (q1.z + q1.w);
      scale[mt][0] = 1.f / fmaxf(sqrtf(s0), 1e-12f);
      scale[mt][1] = 1.f / fmaxf(sqrtf(s1), 1e-12f);
    }
  }

#pragma unroll
  for (int mt = 0; mt < 2; mt++){
    int m = m0 + wr*32 + mt*16 + g;
    int b = m >> 8, t = m & 255;
#pragma unroll
    for (int nt = 0; nt < 4; nt++){
      int d = wn*32 + nt*8 + cq*2;
      size_t off = ((size_t)((b*NH + h)*TT + t))*HD + d;
      *(float2*)&DST[off] = make_float2(v[mt][nt][0]*scale[mt][0],
                                        v[mt][nt][1]*scale[mt][0]);
      *(float2*)&DST[off + 8*HD] = make_float2(v[mt][nt][2]*scale[mt][1],
                                               v[mt][nt][3]*scale[mt][1]);
    }
  }
}

// ------------------------- K2: chunk sums + scan fused ------------------------
__global__ void __launch_bounds__(256,4) k_chunkscan(){
  int vslab = blockIdx.x, bh = blockIdx.y;
  int tid = threadIdx.x;
  int i  = vslab*16 + (tid >> 4);
  int j0 = (tid & 15) * 8;
  __shared__ __align__(16) float ks[CS][HD], vs[CS][HD];
  __shared__ float coef[CS];
  __shared__ float dcs;
  float ckk[8], ckv[8];
#pragma unroll
  for (int u = 0; u < 8; u++){ ckk[u] = 0.f; ckv[u] = 0.f; }

  for (int c = 0; c < NC; c++){
    if (c) __syncthreads();
    {
      const float4* Kp = (const float4*)(g_K + (size_t)(bh*TT + c*CS)*HD);
      const float4* Vp = (const float4*)(g_V + (size_t)(bh*TT + c*CS)*HD);
      ((float4*)ks)[tid] = Kp[tid];
      ((float4*)vs)[tid] = Vp[tid];
    }
    if (tid < CS){
      float s = 0.f;
      for (int u = tid + 1; u < CS; u++) s += g_g[bh*TT + c*CS + u];
      coef[tid] = g_beta[bh*TT + c*CS + tid] * expf(s);
    }
    if (tid == 8){
      float s = 0.f;
      for (int u = 0; u < CS; u++) s += g_g[bh*TT + c*CS + u];
      dcs = expf(s);
    }
    __syncthreads();
    float dc = dcs;
#pragma unroll
    for (int u = 0; u < 8; u++){ ckk[u] *= dc; ckv[u] *= dc; }
#pragma unroll
    for (int s = 0; s < CS; s++){
      float ki = ks[s][i] * coef[s];
      float4 ka = *(const float4*)&ks[s][j0];
      float4 kb = *(const float4*)&ks[s][j0+4];
      float4 va = *(const float4*)&vs[s][j0];
      float4 vb = *(const float4*)&vs[s][j0+4];
      ckk[0] += ki*ka.x; ckk[1] += ki*ka.y; ckk[2] += ki*ka.z; ckk[3] += ki*ka.w;
      ckk[4] += ki*kb.x; ckk[5] += ki*kb.y; ckk[6] += ki*kb.z; ckk[7] += ki*kb.w;
      ckv[0] += ki*va.x; ckv[1] += ki*va.y; ckv[2] += ki*va.z; ckv[3] += ki*va.w;
      ckv[4] += ki*vb.x; ckv[5] += ki*vb.y; ckv[6] += ki*vb.z; ckv[7] += ki*vb.w;
    }
    size_t base = ((size_t)(bh*NC + c) << 14) + (size_t)i*HD + j0;
    *(float4*)&g_Skk[base]   = make_float4(ckk[0], ckk[1], ckk[2], ckk[3]);
    *(float4*)&g_Skk[base+4] = make_float4(ckk[4], ckk[5], ckk[6], ckk[7]);
    *(float4*)&g_Skv[base]   = make_float4(ckv[0], ckv[1], ckv[2], ckv[3]);
    *(float4*)&g_Skv[base+4] = make_float4(ckv[4], ckv[5], ckv[6], ckv[7]);
  }
}

// ------------------------- K3: batched 8-RHS CG solve (256 thr, 2 CTAs/SM) ----
#define PHASE_A(MSM) do { \
  ull y0a=0ull, y0b=0ull, y0c=0ull, y0d=0ull; \
  ull y1a=0ull, y1b=0ull, y1c=0ull, y1d=0ull; \
  _Pragma("unroll") \
  for (int jj = 0; jj < 32; jj++){ \
    ulonglong2 pA = *(const ulonglong2*)&P[mq*32+jj][0]; \
    ulonglong2 pB = *(const ulonglong2*)&P[mq*32+jj][4]; \
    ull h0 = bcast2(hk[jj]); \
    ull h1 = bcast2(hk[32+jj]); \
    ffma2(y0a, h0, pA.x); ffma2(y0b, h0, pA.y); ffma2(y0c, h0, pB.x); ffma2(y0d, h0, pB.y); \
    ffma2(y1a, h1, pA.x); ffma2(y1b, h1, pA.y); ffma2(y1c, h1, pB.x); ffma2(y1d, h1, pB.y); \
  } \
  *(ulonglong2*)&part[mq][mi][0] = make_ulonglong2(y0a, y0b); \
  *(ulonglong2*)&part[mq][mi][4] = make_ulonglong2(y0c, y0d); \
  *(ulonglong2*)&part[mq][mi+64][0] = make_ulonglong2(y1a, y1b); \
  *(ulonglong2*)&part[mq][mi+64][4] = make_ulonglong2(y1c, y1d); \
  { float4 kv_ = *(const float4*)&MSM[warp][lane*4]; \
    _Pragma("unroll") \
    for (int t_ = 0; t_ < 8; t_++){ \
      float4 pv_ = *(const float4*)&PT[t_][lane*4]; \
      float pd_ = kv_.x*pv_.x + kv_.y*pv_.y + kv_.z*pv_.z + kv_.w*pv_.w; \
      pd_ = warp_sum(pd_); \
      if (lane == 0) dots[t_][warp] = pd_; \
    } } \
} while(0)

#define ASM4(OUT) do { \
  float4 ya_ = make_float4(0.f, 0.f, 0.f, 0.f); \
  _Pragma("unroll") \
  for (int q2 = 0; q2 < 4; q2++){ \
    float4 pr_ = *(const float4*)&part[q2][si][t0]; \
    ya_.x += pr_.x; ya_.y += pr_.y; ya_.z += pr_.z; ya_.w += pr_.w; \
  } \
  float yarr_[4] = {ya_.x, ya_.y, ya_.z, ya_.w}; \
  _Pragma("unroll") \
  for (int u = 0; u < 4; u++){ \
    int t_ = t0 + u; \
    float a_ = cdec[t_] * yarr_[u]; \
    float4 d0_ = *(const float4*)&dots[t_][0]; \
    float4 d1_ = *(const float4*)&dots[t_][4]; \
    float4 w0_ = *(const float4*)&Wc[t_][0]; \
    float4 w1_ = *(const float4*)&Wc[t_][4]; \
    a_ += (w0_.x*d0_.x)*ksi[0] + (w0_.y*d0_.y)*ksi[1] \
        + (w0_.z*d0_.z)*ksi[2] + (w0_.w*d0_.w)*ksi[3] \
        + (w1_.x*d1_.x)*ksi[4] + (w1_.y*d1_.y)*ksi[5] \
        + (w1_.z*d1_.z)*ksi[6] + (w1_.w*d1_.w)*ksi[7]; \
    OUT[u] = a_; \
  } \
} while(0)

__global__ void __launch_bounds__(256,2) k_solve(const float* __restrict__ lp,
                                                 const float* __restrict__ onw){
  int c = blockIdx.x, bh = blockIdx.y;
  int b = bh >> 4, h = bh & 15;
  int tid = threadIdx.x;
  int si = tid & 127, sg2 = tid >> 7, lane = tid & 31, warp = tid >> 5;
  int mi = tid & 63, mq = tid >> 6;
  int g0 = bh*TT + c*CS;
  int t0 = sg2*4;

  __shared__ __align__(16) float Ksm[CS][HD], Vsm[CS][HD], Qsm[CS][HD];
  __shared__ __align__(16) float P[HD][12];
  __shared__ __align__(16) float PT[CS][HD+4];
  __shared__ __align__(16) float part[4][HD][12];
  __shared__ __align__(16) float dots[CS][CS];
  __shared__ __align__(16) float Wc[CS][CS];
  __shared__ float cdec[CS];
  __shared__ float lam[HD], dg[HD], gsm[CS], bsm[CS];
  __shared__ __align__(16) float wredA[4][8];
  __shared__ __align__(16) float wredB[4][8];

  {
    const float4* Kp = (const float4*)(g_K + (size_t)g0*HD);
    const float4* Vp = (const float4*)(g_V + (size_t)g0*HD);
    const float4* Qp = (const float4*)(g_Q + (size_t)g0*HD);
    ((float4*)Ksm)[tid] = Kp[tid];
    ((float4*)Qsm)[tid] = Qp[tid];
    ((float4*)Vsm)[tid] = Vp[tid];
  }
  if (tid >= 128 && tid < 136){ gsm[tid-128] = g_g[g0 + tid-128]; bsm[tid-128] = g_beta[g0 + tid-128]; }
  if (tid < 128){
    float zz = lp[h*HD + tid];
    float sp = (zz > 20.f) ? zz : log1pf(expf(zz));
    lam[tid] = sp + 0.25f;
  }
  float hk[64];
  if (c == 0){
#pragma unroll
    for (int jj = 0; jj < 64; jj++) hk[jj] = 0.f;
  } else {
    size_t base = ((size_t)(bh*NC + (c-1)) << 14) + mq*32;
#pragma unroll
    for (int jj = 0; jj < 32; jj += 4){
      float4 a = *(const float4*)&g_Skk[base + (size_t)mi*HD + jj];
      hk[jj] = a.x; hk[jj+1] = a.y; hk[jj+2] = a.z; hk[jj+3] = a.w;
      float4 a2 = *(const float4*)&g_Skk[base + (size_t)(mi+64)*HD + jj];
      hk[32+jj] = a2.x; hk[33+jj] = a2.y; hk[34+jj] = a2.z; hk[35+jj] = a2.w;
    }
  }
  if (mq == (mi >> 5))       dg[mi]      = hk[mi & 31];
  if (mq == 2 + (mi >> 5))   dg[mi + 64] = hk[32 + (mi & 31)];
  __syncthreads();

  if (tid < 64){
    int t_ = tid >> 3, s_ = tid & 7;
    float w = 0.f;
    if (s_ <= t_){
      float s = 0.f;
      for (int u = s_+1; u <= t_; u++) s += gsm[u];
      w = bsm[s_] * expf(s);
    }
    Wc[t_][s_] = w;
  }
  if (tid >= 64 && tid < 72){
    int t_ = tid - 64;
    float s = 0.f;
    for (int u = 0; u <= t_; u++) s += gsm[u];
    cdec[t_] = expf(s);
  }
  __syncthreads();

  float ksi[CS];
#pragma unroll
  for (int s = 0; s < CS; s++) ksi[s] = Ksm[s][si];
  float xv[4], rv[4], pv[4], dloc[4], qv[4];
  unsigned dmask = 0;
#pragma unroll
  for (int u = 0; u < 4; u++){
    int t = t0 + u;
    float diag = cdec[t]*dg[si] + lam[si];
#pragma unroll
    for (int s = 0; s < CS; s++) diag += Wc[t][s] * ksi[s] * ksi[s];
    float x = Qsm[t][si] / (diag + 1e-8f);
    xv[u] = x; P[si][t] = x; PT[t][si] = x;
  }
  __syncthreads();

  PHASE_A(Ksm);
  __syncthreads();
  {
    float av[4];
    ASM4(av);
#pragma unroll
    for (int u = 0; u < 4; u++){
      int t = t0 + u;
      float r = Qsm[t][si] - (av[u] + lam[si]*xv[u]);
      rv[u] = r; pv[u] = r;
      float rr = warp_sum(r*r);
      if (lane == 0) wredA[u][warp] = rr;
      P[si][t] = r; PT[t][si] = r;
    }
  }
  group_bar(sg2);
#pragma unroll
  for (int u = 0; u < 4; u++){
    float4 wv = *(const float4*)&wredA[u][sg2*4];
    dloc[u] = (wv.x + wv.y) + (wv.z + wv.w);
  }
  __syncthreads();

  for (int it = 0; it < NCG; it++){
    PHASE_A(Ksm);
    __syncthreads();
    {
      ASM4(qv);
#pragma unroll
      for (int u = 0; u < 4; u++){
        qv[u] += lam[si] * pv[u];
        float pq = warp_sum(pv[u] * qv[u]);
        if (lane == 0) wredA[u][warp] = pq;
      }
    }
    group_bar(sg2);
#pragma unroll
    for (int u = 0; u < 4; u++){
      float4 wv = *(const float4*)&wredA[u][sg2*4];
      float pq = (wv.x + wv.y) + (wv.z + wv.w);
      if (dloc[u] < 1e-10f) dmask |= 1u << u;
      if (fabsf(pq) < 1e-10f) dmask |= 1u << u;
      float alpha = (dmask >> u & 1u) ? 0.f : dloc[u] / pq;
      xv[u] += alpha * pv[u];
      rv[u] -= alpha * qv[u];
      float rr = warp_sum(rv[u] * rv[u]);
      if (lane == 0) wredB[u][warp] = rr;
    }
    group_bar(sg2);
#pragma unroll
    for (int u = 0; u < 4; u++){
      int t = t0 + u;
      float4 wv = *(const float4*)&wredB[u][sg2*4];
      float dn = (wv.x + wv.y) + (wv.z + wv.w);
      if (!(dmask >> u & 1u)){
        float bet = dn / dloc[u];
        dloc[u] = dn;
        pv[u] = rv[u] + bet * pv[u];
      }
      P[si][t] = pv[u]; PT[t][si] = pv[u];
    }
    __syncthreads();
  }

#pragma unroll
  for (int u = 0; u < 4; u++){
    int t = t0 + u;
    P[si][t] = xv[u]; PT[t][si] = xv[u];
  }
  if (c == 0){
#pragma unroll
    for (int jj = 0; jj < 64; jj++) hk[jj] = 0.f;
  } else {
    size_t base = ((size_t)(bh*NC + (c-1)) << 14) + mq*32;
#pragma unroll
    for (int jj = 0; jj < 32; jj += 4){
      float4 a = *(const float4*)&g_Skv[base + (size_t)mi*HD + jj];
      hk[jj] = a.x; hk[jj+1] = a.y; hk[jj+2] = a.z; hk[jj+3] = a.w;
      float4 a2 = *(const float4*)&g_Skv[base + (size_t)(mi+64)*HD + jj];
      hk[32+jj] = a2.x; hk[33+jj] = a2.y; hk[34+jj] = a2.z; hk[35+jj] = a2.w;
    }
  }
  __syncthreads();
  PHASE_A(Vsm);
  __syncthreads();
  float ov[4];
  ASM4(ov);
#pragma unroll
  for (int u = 0; u < 4; u++){
    float ss = warp_sum(ov[u]*ov[u]);
    if (lane == 0) wredA[u][warp] = ss;
  }
  group_bar(sg2);
  float wnv = onw[si];
#pragma unroll
  for (int u = 0; u < 4; u++){
    int t = t0 + u;
    float4 wv = *(const float4*)&wredA[u][sg2*4];
    float ms = ((wv.x + wv.y) + (wv.z + wv.w)) * (1.f/128.f);
    float rms = sqrtf(ms + 1e-6f);
    int ts = c*CS + t;
    g_Of[(size_t)(b*TT + ts)*HID + h*HD + si] = ov[u] / rms * wnv;
  }
}

// ------------------------- K4: output projection (3xTF32, 64x128 tiles) -------
__global__ void __launch_bounds__(256) k_out(const float* __restrict__ Wo,
                                             float* __restrict__ out){
  __shared__ __align__(16) uint32_t Ah[64][20], Al[64][20];
  __shared__ __align__(16) uint32_t Bh[16][136], Bl[16][136];

  int tid = threadIdx.x;
  int lane = tid & 31, warp = tid >> 5;
  int wr = warp >> 2, wn = warp & 3;
  int g = lane >> 2, cq = lane & 3;
  int m0 = blockIdx.y * 64;
  int n0 = blockIdx.x * 128;

  float acc[2][4][4];
#pragma unroll
  for (int mt = 0; mt < 2; mt++)
#pragma unroll
    for (int nt = 0; nt < 4; nt++)
#pragma unroll
      for (int j = 0; j < 4; j++) acc[mt][nt][j] = 0.f;

  int am = tid >> 2, ak = (tid & 3) * 4;
  int bk0 = tid >> 5, bn0 = (tid & 31) * 4;
  float4 pa, pb[2];
  pa = *(const float4*)&g_Of[(size_t)(m0 + am)*HID + ak];
#pragma unroll
  for (int p = 0; p < 2; p++)
    pb[p] = *(const float4*)&Wo[(size_t)(bk0 + p*8)*HID + n0 + bn0];

  for (int kb = 0; kb < HID; kb += 16){
    {
      float vv[4] = {pa.x, pa.y, pa.z, pa.w};
      uint32_t hi[4], lo[4];
#pragma unroll
      for (int e = 0; e < 4; e++){
        hi[e] = f2tf32(vv[e]);
        lo[e] = f2tf32(vv[e] - __uint_as_float(hi[e]));
      }
      *(uint4*)&Ah[am][ak] = make_uint4(hi[0], hi[1], hi[2], hi[3]);
      *(uint4*)&Al[am][ak] = make_uint4(lo[0], lo[1], lo[2], lo[3]);
#pragma unroll
      for (int p = 0; p < 2; p++){
        float wv[4] = {pb[p].x, pb[p].y, pb[p].z, pb[p].w};
#pragma unroll
        for (int e = 0; e < 4; e++){
          hi[e] = f2tf32(wv[e]);
          lo[e] = f2tf32(wv[e] - __uint_as_float(hi[e]));
        }
        *(uint4*)&Bh[bk0 + p*8][bn0] = make_uint4(hi[0], hi[1], hi[2], hi[3]);
        *(uint4*)&Bl[bk0 + p*8][bn0] = make_uint4(lo[0], lo[1], lo[2], lo[3]);
      }
    }
    __syncthreads();
    if (kb + 16 < HID){
      pa = *(const float4*)&g_Of[(size_t)(m0 + am)*HID + kb + 16 + ak];
#pragma unroll
      for (int p = 0; p < 2; p++)
        pb[p] = *(const float4*)&Wo[(size_t)(kb + 16 + bk0 + p*8)*HID + n0 + bn0];
    }
#pragma unroll
    for (int ks = 0; ks < 2; ks++){
      int k0 = ks*8 + cq;
      uint32_t ah[2][4], al[2][4];
#pragma unroll
      for (int mt = 0; mt < 2; mt++){
        int mb = wr*32 + mt*16;
        ah[mt][0] = Ah[mb+g][k0];   ah[mt][1] = Ah[mb+g+8][k0];
        ah[mt][2] = Ah[mb+g][k0+4]; ah[mt][3] = Ah[mb+g+8][k0+4];
        al[mt][0] = Al[mb+g][k0];   al[mt][1] = Al[mb+g+8][k0];
        al[mt][2] = Al[mb+g][k0+4]; al[mt][3] = Al[mb+g+8][k0+4];
      }
#pragma unroll
      for (int nt = 0; nt < 4; nt++){
        int nb = wn*32 + nt*8;
        uint32_t bh0 = Bh[k0][nb+g], bh1 = Bh[k0+4][nb+g];
        uint32_t bl0 = Bl[k0][nb+g], bl1 = Bl[k0+4][nb+g];
#pragma unroll
        for (int mt = 0; mt < 2; mt++){
          MMA_TF32(acc[mt][nt], ah[mt][0], ah[mt][1], ah[mt][2], ah[mt][3], bl0, bl1);
          MMA_TF32(acc[mt][nt], al[mt][0], al[mt][1], al[mt][2], al[mt][3], bh0, bh1);
          MMA_TF32(acc[mt][nt], ah[mt][0], ah[mt][1], ah[mt][2], ah[mt][3], bh0, bh1);
        }
      }
    }
    __syncthreads();
  }

#pragma unroll
  for (int mt = 0; mt < 2; mt++){
    int m = m0 + wr*32 + mt*16 + g;
#pragma unroll
    for (int nt = 0; nt < 4; nt++){
      int cc = n0 + wn*32 + nt*8 + cq*2;
      *(float2*)&out[(size_t)m*HID + cc]     = make_float2(acc[mt][nt][0], acc[mt][nt][1]);
      *(float2*)&out[(size_t)(m+8)*HID + cc] = make_float2(acc[mt][nt][2], acc[mt][nt][3]);
    }
  }
}

// ------------------------- launcher -------------------------
extern "C" void kernel_launch(void* const* d_in, const int* in_sizes, int n_in,
                              void* d_out, int out_size){
  const float* x    = (const float*)d_in[0];
  const float* Wq   = (const float*)d_in[1];
  const float* Wk   = (const float*)d_in[2];
  const float* Wv   = (const float*)d_in[3];
  const float* Wa   = (const float*)d_in[4];
  const float* ba   = (const float*)d_in[5];
  const float* Wb   = (const float*)d_in[6];
  const float* bb   = (const float*)d_in[7];
  const float* lpar = (const float*)d_in[8];
  const float* onw  = (const float*)d_in[9];
  const float* Wo   = (const float*)d_in[10];
  float* out = (float*)d_out;

  k_qkv<<<dim3(16, 8, 4), 256>>>(x, Wq, Wk, Wv, Wa, ba, Wb, bb);  // gates fused
  k_chunkscan<<<dim3(8, BH), 256>>>();
  k_solve<<<dim3(NC, BH), 256>>>(lpar, onw);
  k_out<<<dim3(16, 8), 256>>>(Wo, out);
}

// round 15
// speedup vs baseline: 1.0569x; 1.0172x over previous
#include <cuda_runtime.h>
#include <math.h>
#include <stdint.h>

#define BN   2
#define TT   256
#define HID  2048
#define NOUT 2048
#define NH   16
#define HD   128
#define BH   32
#define CS   8
#define NC   32
#define NCG  7
#define MROWS (BN*TT)

typedef unsigned long long ull;

// dynamic smem layout (bytes) for the TF32 GEMM tiles, double-buffered
#define AH_OFF   0u          // uint32[2][64][20]  = 10240
#define AL_OFF   10240u      // uint32[2][64][20]  = 10240
#define BH_OFF   20480u      // uint32[2][16][136] = 17408
#define BL_OFF   37888u      // uint32[2][16][136] = 17408
#define L2S_OFF  55296u      // float[64][4]       = 1024
#define QKV_SMEM 56320u
#define OUT_SMEM 55296u

// ------------------------- scratch (device globals) -------------------------
__device__ float g_Q[BH*TT*HD];
__device__ float g_K[BH*TT*HD];
__device__ float g_V[BH*TT*HD];
__device__ float g_Of[MROWS*HID];
__device__ float g_g[BH*TT];
__device__ float g_beta[BH*TT];
__device__ float g_Skk[BH*NC*HD*HD];
__device__ float g_Skv[BH*NC*HD*HD];

// ------------------------- helpers -------------------------
__device__ __forceinline__ float warp_sum(float v){
#pragma unroll
  for (int o = 16; o; o >>= 1) v += __shfl_xor_sync(0xffffffffu, v, o);
  return v;
}
__device__ __forceinline__ ull bcast2(float x){
  ull r; asm("mov.b64 %0, {%1, %1};" : "=l"(r) : "f"(x)); return r;
}
__device__ __forceinline__ void ffma2(ull& d, ull a, ull b){
  asm("fma.rn.f32x2 %0, %1, %2, %0;" : "+l"(d) : "l"(a), "l"(b));
}
__device__ __forceinline__ float2 unpack2(ull v){
  float2 f; asm("mov.b64 {%0, %1}, %2;" : "=f"(f.x), "=f"(f.y) : "l"(v)); return f;
}
__device__ __forceinline__ float silu(float z){ return z / (1.f + expf(-z)); }
__device__ __forceinline__ void group_bar(int g){
  asm volatile("bar.sync %0, %1;" :: "r"(1 + g), "r"(128) : "memory");
}
__device__ __forceinline__ uint32_t f2tf32(float v){
  uint32_t r; asm("cvt.rna.tf32.f32 %0, %1;" : "=r"(r) : "f"(v)); return r;
}

#define MMA_TF32(d, a0,a1,a2,a3, b0,b1) \
  asm volatile("mma.sync.aligned.m16n8k8.row.col.f32.tf32.tf32.f32 " \
    "{%0,%1,%2,%3}, {%4,%5,%6,%7}, {%8,%9}, {%0,%1,%2,%3};" \
    : "+f"((d)[0]),"+f"((d)[1]),"+f"((d)[2]),"+f"((d)[3]) \
    : "r"(a0),"r"(a1),"r"(a2),"r"(a3), "r"(b0),"r"(b1))

// ------------------------- K1: QKV GEMM (3xTF32, dbl-buf dyn-smem) ------------
__global__ void __launch_bounds__(256,2) k_qkv(const float* __restrict__ X,
                                               const float* __restrict__ Wq,
                                               const float* __restrict__ Wk,
                                               const float* __restrict__ Wv,
                                               const float* __restrict__ Wa,
                                               const float* __restrict__ ba,
                                               const float* __restrict__ Wb,
                                               const float* __restrict__ bb){
  extern __shared__ __align__(16) char smem_raw[];
  int z = blockIdx.z;
  int tid = threadIdx.x;

  if (z == 3){
    // ---- gates path (reuses dynamic smem) ----
    float* xr = (float*)smem_raw;                   // [2048]
    float (*red)[32] = (float(*)[32])(smem_raw + 8192);
    int cta = blockIdx.y * 16 + blockIdx.x;         // 0..127
    for (int r4 = 0; r4 < 4; r4++){
      int row = cta*4 + r4;
      int b = row >> 8, t = row & 255;
      const float4* xp = (const float4*)(X + (size_t)row * HID);
      for (int idx = tid; idx < HID/4; idx += 256)
        *(float4*)&xr[idx*4] = xp[idx];
      __syncthreads();
      int o = tid & 31, k8 = tid >> 5;
      float partial = 0.f;
      if (o < 16){
        for (int cc = k8*256; cc < k8*256+256; cc++) partial += xr[cc] * Wa[cc*NH + o];
      } else {
        int oo = o - 16;
        for (int cc = k8*256; cc < k8*256+256; cc++) partial += xr[cc] * Wb[cc*NH + oo];
      }
      red[k8][o] = partial;
      __syncthreads();
      if (tid < 32){
        float v = 0.f;
#pragma unroll
        for (int u = 0; u < 8; u++) v += red[u][tid];
        if (tid < 16){
          float zz = v + ba[tid];
          float ls = (zz >= 0.f) ? -log1pf(expf(-zz)) : (zz - log1pf(expf(zz)));
          g_g[(b*NH + tid)*TT + t] = ls;
        } else {
          int hh = tid - 16;
          float zz = v + bb[hh];
          g_beta[(b*NH + hh)*TT + t] = 1.f / (1.f + expf(-zz));
        }
      }
      __syncthreads();
    }
    return;
  }

  uint32_t (*Ah)[64][20]  = (uint32_t(*)[64][20])(smem_raw + AH_OFF);
  uint32_t (*Al)[64][20]  = (uint32_t(*)[64][20])(smem_raw + AL_OFF);
  uint32_t (*Bh)[16][136] = (uint32_t(*)[16][136])(smem_raw + BH_OFF);
  uint32_t (*Bl)[16][136] = (uint32_t(*)[16][136])(smem_raw + BL_OFF);
  float (*l2s)[4]         = (float(*)[4])(smem_raw + L2S_OFF);

  const float* W = z == 0 ? Wq : (z == 1 ? Wk : Wv);
  float* DST     = z == 0 ? g_Q : (z == 1 ? g_K : g_V);

  int lane = tid & 31, warp = tid >> 5;
  int wr = warp >> 2, wn = warp & 3;
  int g = lane >> 2, cq = lane & 3;
  int m0 = blockIdx.y * 64;
  int h = blockIdx.x;
  int n0 = h * 128;

  float acc[2][4][4];
#pragma unroll
  for (int mt = 0; mt < 2; mt++)
#pragma unroll
    for (int nt = 0; nt < 4; nt++)
#pragma unroll
      for (int j = 0; j < 4; j++) acc[mt][nt][j] = 0.f;

  int am = tid >> 2, ak = (tid & 3) * 4;
  int bk0 = tid >> 5, bn0 = (tid & 31) * 4;
  float4 pa, pb[2];
  pa = *(const float4*)&X[(size_t)(m0 + am)*HID + ak];
#pragma unroll
  for (int p = 0; p < 2; p++)
    pb[p] = *(const float4*)&W[(size_t)(bk0 + p*8)*NOUT + n0 + bn0];

  for (int kb = 0; kb < HID; kb += 16){
    int cur = (kb >> 4) & 1;
    {
      float vv[4] = {pa.x, pa.y, pa.z, pa.w};
      uint32_t hi[4], lo[4];
#pragma unroll
      for (int e = 0; e < 4; e++){
        hi[e] = f2tf32(vv[e]);
        lo[e] = f2tf32(vv[e] - __uint_as_float(hi[e]));
      }
      *(uint4*)&Ah[cur][am][ak] = make_uint4(hi[0], hi[1], hi[2], hi[3]);
      *(uint4*)&Al[cur][am][ak] = make_uint4(lo[0], lo[1], lo[2], lo[3]);
#pragma unroll
      for (int p = 0; p < 2; p++){
        float wv[4] = {pb[p].x, pb[p].y, pb[p].z, pb[p].w};
#pragma unroll
        for (int e = 0; e < 4; e++){
          hi[e] = f2tf32(wv[e]);
          lo[e] = f2tf32(wv[e] - __uint_as_float(hi[e]));
        }
        *(uint4*)&Bh[cur][bk0 + p*8][bn0] = make_uint4(hi[0], hi[1], hi[2], hi[3]);
        *(uint4*)&Bl[cur][bk0 + p*8][bn0] = make_uint4(lo[0], lo[1], lo[2], lo[3]);
      }
    }
    __syncthreads();
    if (kb + 16 < HID){
      pa = *(const float4*)&X[(size_t)(m0 + am)*HID + kb + 16 + ak];
#pragma unroll
      for (int p = 0; p < 2; p++)
        pb[p] = *(const float4*)&W[(size_t)(kb + 16 + bk0 + p*8)*NOUT + n0 + bn0];
    }
#pragma unroll
    for (int ks = 0; ks < 2; ks++){
      int k0 = ks*8 + cq;
      uint32_t ah[2][4], al[2][4];
#pragma unroll
      for (int mt = 0; mt < 2; mt++){
        int mb = wr*32 + mt*16;
        ah[mt][0] = Ah[cur][mb+g][k0];   ah[mt][1] = Ah[cur][mb+g+8][k0];
        ah[mt][2] = Ah[cur][mb+g][k0+4]; ah[mt][3] = Ah[cur][mb+g+8][k0+4];
        al[mt][0] = Al[cur][mb+g][k0];   al[mt][1] = Al[cur][mb+g+8][k0];
        al[mt][2] = Al[cur][mb+g][k0+4]; al[mt][3] = Al[cur][mb+g+8][k0+4];
      }
#pragma unroll
      for (int nt = 0; nt < 4; nt++){
        int nb = wn*32 + nt*8;
        uint32_t bh0 = Bh[cur][k0][nb+g], bh1 = Bh[cur][k0+4][nb+g];
        uint32_t bl0 = Bl[cur][k0][nb+g], bl1 = Bl[cur][k0+4][nb+g];
#pragma unroll
        for (int mt = 0; mt < 2; mt++){
          MMA_TF32(acc[mt][nt], ah[mt][0], ah[mt][1], ah[mt][2], ah[mt][3], bl0, bl1);
          MMA_TF32(acc[mt][nt], al[mt][0], al[mt][1], al[mt][2], al[mt][3], bh0, bh1);
          MMA_TF32(acc[mt][nt], ah[mt][0], ah[mt][1], ah[mt][2], ah[mt][3], bh0, bh1);
        }
      }
    }
    // no trailing sync: next store targets the other buffer
  }

  float v[2][4][4];
#pragma unroll
  for (int mt = 0; mt < 2; mt++)
#pragma unroll
    for (int nt = 0; nt < 4; nt++)
#pragma unroll
      for (int j = 0; j < 4; j++) v[mt][nt][j] = silu(acc[mt][nt][j]);

  float scale[2][2] = {{1.f,1.f},{1.f,1.f}};
  if (z < 2){
#pragma unroll
    for (int mt = 0; mt < 2; mt++){
      float s0 = 0.f, s1 = 0.f;
#pragma unroll
      for (int nt = 0; nt < 4; nt++){
        s0 += v[mt][nt][0]*v[mt][nt][0] + v[mt][nt][1]*v[mt][nt][1];
        s1 += v[mt][nt][2]*v[mt][nt][2] + v[mt][nt][3]*v[mt][nt][3];
      }
      s0 += __shfl_xor_sync(0xffffffffu, s0, 1);
      s0 += __shfl_xor_sync(0xffffffffu, s0, 2);
      s1 += __shfl_xor_sync(0xffffffffu, s1, 1);
      s1 += __shfl_xor_sync(0xffffffffu, s1, 2);
      if (cq == 0){
        l2s[wr*32 + mt*16 + g][wn]     = s0;
        l2s[wr*32 + mt*16 + g + 8][wn] = s1;
      }
    }
    __syncthreads();
#pragma unroll
    for (int mt = 0; mt < 2; mt++){
      float4 q0 = *(const float4*)&l2s[wr*32 + mt*16 + g][0];
      float4 q1 = *(const float4*)&l2s[wr*32 + mt*16 + g + 8][0];
      float s0 = (q0.x + q0.y) + (q0.z + q0.w);
      float s1 = (q1.x + q1.y) + (q1.z + q1.w);
      scale[mt][0] = 1.f / fmaxf(sqrtf(s0), 1e-12f);
      scale[mt][1] = 1.f / fmaxf(sqrtf(s1), 1e-12f);
    }
  }

#pragma unroll
  for (int mt = 0; mt < 2; mt++){
    int m = m0 + wr*32 + mt*16 + g;
    int b = m >> 8, t = m & 255;
#pragma unroll
    for (int nt = 0; nt < 4; nt++){
      int d = wn*32 + nt*8 + cq*2;
      size_t off = ((size_t)((b*NH + h)*TT + t))*HD + d;
      *(float2*)&DST[off] = make_float2(v[mt][nt][0]*scale[mt][0],
                                        v[mt][nt][1]*scale[mt][0]);
      *(float2*)&DST[off + 8*HD] = make_float2(v[mt][nt][2]*scale[mt][1],
                                               v[mt][nt][3]*scale[mt][1]);
    }
  }
}

// ------------------------- K2: chunk sums + scan fused ------------------------
__global__ void __launch_bounds__(256,4) k_chunkscan(){
  int vslab = blockIdx.x, bh = blockIdx.y;
  int tid = threadIdx.x;
  int i  = vslab*16 + (tid >> 4);
  int j0 = (tid & 15) * 8;
  __shared__ __align__(16) float ks[CS][HD], vs[CS][HD];
  __shared__ float coef[CS];
  __shared__ float dcs;
  float ckk[8], ckv[8];
#pragma unroll
  for (int u = 0; u < 8; u++){ ckk[u] = 0.f; ckv[u] = 0.f; }

  for (int c = 0; c < NC; c++){
    if (c) __syncthreads();
    {
      const float4* Kp = (const float4*)(g_K + (size_t)(bh*TT + c*CS)*HD);
      const float4* Vp = (const float4*)(g_V + (size_t)(bh*TT + c*CS)*HD);
      ((float4*)ks)[tid] = Kp[tid];
      ((float4*)vs)[tid] = Vp[tid];
    }
    if (tid < CS){
      float s = 0.f;
      for (int u = tid + 1; u < CS; u++) s += g_g[bh*TT + c*CS + u];
      coef[tid] = g_beta[bh*TT + c*CS + tid] * expf(s);
    }
    if (tid == 8){
      float s = 0.f;
      for (int u = 0; u < CS; u++) s += g_g[bh*TT + c*CS + u];
      dcs = expf(s);
    }
    __syncthreads();
    float dc = dcs;
#pragma unroll
    for (int u = 0; u < 8; u++){ ckk[u] *= dc; ckv[u] *= dc; }
#pragma unroll
    for (int s = 0; s < CS; s++){
      float ki = ks[s][i] * coef[s];
      float4 ka = *(const float4*)&ks[s][j0];
      float4 kb = *(const float4*)&ks[s][j0+4];
      float4 va = *(const float4*)&vs[s][j0];
      float4 vb = *(const float4*)&vs[s][j0+4];
      ckk[0] += ki*ka.x; ckk[1] += ki*ka.y; ckk[2] += ki*ka.z; ckk[3] += ki*ka.w;
      ckk[4] += ki*kb.x; ckk[5] += ki*kb.y; ckk[6] += ki*kb.z; ckk[7] += ki*kb.w;
      ckv[0] += ki*va.x; ckv[1] += ki*va.y; ckv[2] += ki*va.z; ckv[3] += ki*va.w;
      ckv[4] += ki*vb.x; ckv[5] += ki*vb.y; ckv[6] += ki*vb.z; ckv[7] += ki*vb.w;
    }
    size_t base = ((size_t)(bh*NC + c) << 14) + (size_t)i*HD + j0;
    *(float4*)&g_Skk[base]   = make_float4(ckk[0], ckk[1], ckk[2], ckk[3]);
    *(float4*)&g_Skk[base+4] = make_float4(ckk[4], ckk[5], ckk[6], ckk[7]);
    *(float4*)&g_Skv[base]   = make_float4(ckv[0], ckv[1], ckv[2], ckv[3]);
    *(float4*)&g_Skv[base+4] = make_float4(ckv[4], ckv[5], ckv[6], ckv[7]);
  }
}

// ------------------------- K3: batched 8-RHS CG solve (256 thr, 2 CTAs/SM) ----
#define PHASE_A(MSM) do { \
  ull y0a=0ull, y0b=0ull, y0c=0ull, y0d=0ull; \
  ull y1a=0ull, y1b=0ull, y1c=0ull, y1d=0ull; \
  _Pragma("unroll") \
  for (int jj = 0; jj < 32; jj++){ \
    ulonglong2 pA = *(const ulonglong2*)&P[mq*32+jj][0]; \
    ulonglong2 pB = *(const ulonglong2*)&P[mq*32+jj][4]; \
    ull h0 = bcast2(hk[jj]); \
    ull h1 = bcast2(hk[32+jj]); \
    ffma2(y0a, h0, pA.x); ffma2(y0b, h0, pA.y); ffma2(y0c, h0, pB.x); ffma2(y0d, h0, pB.y); \
    ffma2(y1a, h1, pA.x); ffma2(y1b, h1, pA.y); ffma2(y1c, h1, pB.x); ffma2(y1d, h1, pB.y); \
  } \
  *(ulonglong2*)&part[mq][mi][0] = make_ulonglong2(y0a, y0b); \
  *(ulonglong2*)&part[mq][mi][4] = make_ulonglong2(y0c, y0d); \
  *(ulonglong2*)&part[mq][mi+64][0] = make_ulonglong2(y1a, y1b); \
  *(ulonglong2*)&part[mq][mi+64][4] = make_ulonglong2(y1c, y1d); \
  { float4 kv_ = *(const float4*)&MSM[warp][lane*4]; \
    _Pragma("unroll") \
    for (int t_ = 0; t_ < 8; t_++){ \
      float4 pv_ = *(const float4*)&PT[t_][lane*4]; \
      float pd_ = kv_.x*pv_.x + kv_.y*pv_.y + kv_.z*pv_.z + kv_.w*pv_.w; \
      pd_ = warp_sum(pd_); \
      if (lane == 0) dots[t_][warp] = pd_; \
    } } \
} while(0)

#define ASM4(OUT) do { \
  float4 ya_ = make_float4(0.f, 0.f, 0.f, 0.f); \
  _Pragma("unroll") \
  for (int q2 = 0; q2 < 4; q2++){ \
    float4 pr_ = *(const float4*)&part[q2][si][t0]; \
    ya_.x += pr_.x; ya_.y += pr_.y; ya_.z += pr_.z; ya_.w += pr_.w; \
  } \
  float yarr_[4] = {ya_.x, ya_.y, ya_.z, ya_.w}; \
  _Pragma("unroll") \
  for (int u = 0; u < 4; u++){ \
    int t_ = t0 + u; \
    float a_ = cdec[t_] * yarr_[u]; \
    float4 d0_ = *(const float4*)&dots[t_][0]; \
    float4 d1_ = *(const float4*)&dots[t_][4]; \
    float4 w0_ = *(const float4*)&Wc[t_][0]; \
    float4 w1_ = *(const float4*)&Wc[t_][4]; \
    a_ += (w0_.x*d0_.x)*ksi[0] + (w0_.y*d0_.y)*ksi[1] \
        + (w0_.z*d0_.z)*ksi[2] + (w0_.w*d0_.w)*ksi[3] \
        + (w1_.x*d1_.x)*ksi[4] + (w1_.y*d1_.y)*ksi[5] \
        + (w1_.z*d1_.z)*ksi[6] + (w1_.w*d1_.w)*ksi[7]; \
    OUT[u] = a_; \
  } \
} while(0)

__global__ void __launch_bounds__(256,2) k_solve(const float* __restrict__ lp,
                                                 const float* __restrict__ onw){
  int c = blockIdx.x, bh = blockIdx.y;
  int b = bh >> 4, h = bh & 15;
  int tid = threadIdx.x;
  int si = tid & 127, sg2 = tid >> 7, lane = tid & 31, warp = tid >> 5;
  int mi = tid & 63, mq = tid >> 6;
  int g0 = bh*TT + c*CS;
  int t0 = sg2*4;

  __shared__ __align__(16) float Ksm[CS][HD], Vsm[CS][HD], Qsm[CS][HD];
  __shared__ __align__(16) float P[HD][12];
  __shared__ __align__(16) float PT[CS][HD+4];
  __shared__ __align__(16) float part[4][HD][12];
  __shared__ __align__(16) float dots[CS][CS];
  __shared__ __align__(16) float Wc[CS][CS];
  __shared__ float cdec[CS];
  __shared__ float lam[HD], dg[HD], gsm[CS], bsm[CS];
  __shared__ __align__(16) float wredA[4][8];
  __shared__ __align__(16) float wredB[4][8];

  {
    const float4* Kp = (const float4*)(g_K + (size_t)g0*HD);
    const float4* Vp = (const float4*)(g_V + (size_t)g0*HD);
    const float4* Qp = (const float4*)(g_Q + (size_t)g0*HD);
    ((float4*)Ksm)[tid] = Kp[tid];
    ((float4*)Qsm)[tid] = Qp[tid];
    ((float4*)Vsm)[tid] = Vp[tid];
  }
  if (tid >= 128 && tid < 136){ gsm[tid-128] = g_g[g0 + tid-128]; bsm[tid-128] = g_beta[g0 + tid-128]; }
  if (tid < 128){
    float zz = lp[h*HD + tid];
    float sp = (zz > 20.f) ? zz : log1pf(expf(zz));
    lam[tid] = sp + 0.25f;
  }
  float hk[64];
  if (c == 0){
#pragma unroll
    for (int jj = 0; jj < 64; jj++) hk[jj] = 0.f;
  } else {
    size_t base = ((size_t)(bh*NC + (c-1)) << 14) + mq*32;
#pragma unroll
    for (int jj = 0; jj < 32; jj += 4){
      float4 a = *(const float4*)&g_Skk[base + (size_t)mi*HD + jj];
      hk[jj] = a.x; hk[jj+1] = a.y; hk[jj+2] = a.z; hk[jj+3] = a.w;
      float4 a2 = *(const float4*)&g_Skk[base + (size_t)(mi+64)*HD + jj];
      hk[32+jj] = a2.x; hk[33+jj] = a2.y; hk[34+jj] = a2.z; hk[35+jj] = a2.w;
    }
  }
  if (mq == (mi >> 5))       dg[mi]      = hk[mi & 31];
  if (mq == 2 + (mi >> 5))   dg[mi + 64] = hk[32 + (mi & 31)];
  __syncthreads();

  if (tid < 64){
    int t_ = tid >> 3, s_ = tid & 7;
    float w = 0.f;
    if (s_ <= t_){
      float s = 0.f;
      for (int u = s_+1; u <= t_; u++) s += gsm[u];
      w = bsm[s_] * expf(s);
    }
    Wc[t_][s_] = w;
  }
  if (tid >= 64 && tid < 72){
    int t_ = tid - 64;
    float s = 0.f;
    for (int u = 0; u <= t_; u++) s += gsm[u];
    cdec[t_] = expf(s);
  }
  __syncthreads();

  float ksi[CS];
#pragma unroll
  for (int s = 0; s < CS; s++) ksi[s] = Ksm[s][si];
  float xv[4], rv[4], pv[4], dloc[4], qv[4];
  unsigned dmask = 0;
#pragma unroll
  for (int u = 0; u < 4; u++){
    int t = t0 + u;
    float diag = cdec[t]*dg[si] + lam[si];
#pragma unroll
    for (int s = 0; s < CS; s++) diag += Wc[t][s] * ksi[s] * ksi[s];
    float x = Qsm[t][si] / (diag + 1e-8f);
    xv[u] = x; P[si][t] = x; PT[t][si] = x;
  }
  __syncthreads();

  PHASE_A(Ksm);
  __syncthreads();
  {
    float av[4];
    ASM4(av);
#pragma unroll
    for (int u = 0; u < 4; u++){
      int t = t0 + u;
      float r = Qsm[t][si] - (av[u] + lam[si]*xv[u]);
      rv[u] = r; pv[u] = r;
      float rr = warp_sum(r*r);
      if (lane == 0) wredA[u][warp] = rr;
      P[si][t] = r; PT[t][si] = r;
    }
  }
  group_bar(sg2);
#pragma unroll
  for (int u = 0; u < 4; u++){
    float4 wv = *(const float4*)&wredA[u][sg2*4];
    dloc[u] = (wv.x + wv.y) + (wv.z + wv.w);
  }
  __syncthreads();

  for (int it = 0; it < NCG; it++){
    PHASE_A(Ksm);
    __syncthreads();
    {
      ASM4(qv);
#pragma unroll
      for (int u = 0; u < 4; u++){
        qv[u] += lam[si] * pv[u];
        float pq = warp_sum(pv[u] * qv[u]);
        if (lane == 0) wredA[u][warp] = pq;
      }
    }
    group_bar(sg2);
#pragma unroll
    for (int u = 0; u < 4; u++){
      float4 wv = *(const float4*)&wredA[u][sg2*4];
      float pq = (wv.x + wv.y) + (wv.z + wv.w);
      if (dloc[u] < 1e-10f) dmask |= 1u << u;
      if (fabsf(pq) < 1e-10f) dmask |= 1u << u;
      float alpha = (dmask >> u & 1u) ? 0.f : dloc[u] / pq;
      xv[u] += alpha * pv[u];
      rv[u] -= alpha * qv[u];
      float rr = warp_sum(rv[u] * rv[u]);
      if (lane == 0) wredB[u][warp] = rr;
    }
    group_bar(sg2);
#pragma unroll
    for (int u = 0; u < 4; u++){
      int t = t0 + u;
      float4 wv = *(const float4*)&wredB[u][sg2*4];
      float dn = (wv.x + wv.y) + (wv.z + wv.w);
      if (!(dmask >> u & 1u)){
        float bet = dn / dloc[u];
        dloc[u] = dn;
        pv[u] = rv[u] + bet * pv[u];
      }
      P[si][t] = pv[u]; PT[t][si] = pv[u];
    }
    __syncthreads();
  }

#pragma unroll
  for (int u = 0; u < 4; u++){
    int t = t0 + u;
    P[si][t] = xv[u]; PT[t][si] = xv[u];
  }
  if (c == 0){
#pragma unroll
    for (int jj = 0; jj < 64; jj++) hk[jj] = 0.f;
  } else {
    size_t base = ((size_t)(bh*NC + (c-1)) << 14) + mq*32;
#pragma unroll
    for (int jj = 0; jj < 32; jj += 4){
      float4 a = *(const float4*)&g_Skv[base + (size_t)mi*HD + jj];
      hk[jj] = a.x; hk[jj+1] = a.y; hk[jj+2] = a.z; hk[jj+3] = a.w;
      float4 a2 = *(const float4*)&g_Skv[base + (size_t)(mi+64)*HD + jj];
      hk[32+jj] = a2.x; hk[33+jj] = a2.y; hk[34+jj] = a2.z; hk[35+jj] = a2.w;
    }
  }
  __syncthreads();
  PHASE_A(Vsm);
  __syncthreads();
  float ov[4];
  ASM4(ov);
#pragma unroll
  for (int u = 0; u < 4; u++){
    float ss = warp_sum(ov[u]*ov[u]);
    if (lane == 0) wredA[u][warp] = ss;
  }
  group_bar(sg2);
  float wnv = onw[si];
#pragma unroll
  for (int u = 0; u < 4; u++){
    int t = t0 + u;
    float4 wv = *(const float4*)&wredA[u][sg2*4];
    float ms = ((wv.x + wv.y) + (wv.z + wv.w)) * (1.f/128.f);
    float rms = sqrtf(ms + 1e-6f);
    int ts = c*CS + t;
    g_Of[(size_t)(b*TT + ts)*HID + h*HD + si] = ov[u] / rms * wnv;
  }
}

// ------------------------- K4: output projection (3xTF32, dbl-buf dyn-smem) ---
__global__ void __launch_bounds__(256) k_out(const float* __restrict__ Wo,
                                             float* __restrict__ out){
  extern __shared__ __align__(16) char smem_raw[];
  uint32_t (*Ah)[64][20]  = (uint32_t(*)[64][20])(smem_raw + AH_OFF);
  uint32_t (*Al)[64][20]  = (uint32_t(*)[64][20])(smem_raw + AL_OFF);
  uint32_t (*Bh)[16][136] = (uint32_t(*)[16][136])(smem_raw + BH_OFF);
  uint32_t (*Bl)[16][136] = (uint32_t(*)[16][136])(smem_raw + BL_OFF);

  int tid = threadIdx.x;
  int lane = tid & 31, warp = tid >> 5;
  int wr = warp >> 2, wn = warp & 3;
  int g = lane >> 2, cq = lane & 3;
  int m0 = blockIdx.y * 64;
  int n0 = blockIdx.x * 128;

  float acc[2][4][4];
#pragma unroll
  for (int mt = 0; mt < 2; mt++)
#pragma unroll
    for (int nt = 0; nt < 4; nt++)
#pragma unroll
      for (int j = 0; j < 4; j++) acc[mt][nt][j] = 0.f;

  int am = tid >> 2, ak = (tid & 3) * 4;
  int bk0 = tid >> 5, bn0 = (tid & 31) * 4;
  float4 pa, pb[2];
  pa = *(const float4*)&g_Of[(size_t)(m0 + am)*HID + ak];
#pragma unroll
  for (int p = 0; p < 2; p++)
    pb[p] = *(const float4*)&Wo[(size_t)(bk0 + p*8)*HID + n0 + bn0];

  for (int kb = 0; kb < HID; kb += 16){
    int cur = (kb >> 4) & 1;
    {
      float vv[4] = {pa.x, pa.y, pa.z, pa.w};
      uint32_t hi[4], lo[4];
#pragma unroll
      for (int e = 0; e < 4; e++){
        hi[e] = f2tf32(vv[e]);
        lo[e] = f2tf32(vv[e] - __uint_as_float(hi[e]));
      }
      *(uint4*)&Ah[cur][am][ak] = make_uint4(hi[0], hi[1], hi[2], hi[3]);
      *(uint4*)&Al[cur][am][ak] = make_uint4(lo[0], lo[1], lo[2], lo[3]);
#pragma unroll
      for (int p = 0; p < 2; p++){
        float wv[4] = {pb[p].x, pb[p].y, pb[p].z, pb[p].w};
#pragma unroll
        for (int e = 0; e < 4; e++){
          hi[e] = f2tf32(wv[e]);
          lo[e] = f2tf32(wv[e] - __uint_as_float(hi[e]));
        }
        *(uint4*)&Bh[cur][bk0 + p*8][bn0] = make_uint4(hi[0], hi[1], hi[2], hi[3]);
        *(uint4*)&Bl[cur][bk0 + p*8][bn0] = make_uint4(lo[0], lo[1], lo[2], lo[3]);
      }
    }
    __syncthreads();
    if (kb + 16 < HID){
      pa = *(const float4*)&g_Of[(size_t)(m0 + am)*HID + kb + 16 + ak];
#pragma unroll
      for (int p = 0; p < 2; p++)
        pb[p] = *(const float4*)&Wo[(size_t)(kb + 16 + bk0 + p*8)*HID + n0 + bn0];
    }
#pragma unroll
    for (int ks = 0; ks < 2; ks++){
      int k0 = ks*8 + cq;
      uint32_t ah[2][4], al[2][4];
#pragma unroll
      for (int mt = 0; mt < 2; mt++){
        int mb = wr*32 + mt*16;
        ah[mt][0] = Ah[cur][mb+g][k0];   ah[mt][1] = Ah[cur][mb+g+8][k0];
        ah[mt][2] = Ah[cur][mb+g][k0+4]; ah[mt][3] = Ah[cur][mb+g+8][k0+4];
        al[mt][0] = Al[cur][mb+g][k0];   al[mt][1] = Al[cur][mb+g+8][k0];
        al[mt][2] = Al[cur][mb+g][k0+4]; al[mt][3] = Al[cur][mb+g+8][k0+4];
      }
#pragma unroll
      for (int nt = 0; nt < 4; nt++){
        int nb = wn*32 + nt*8;
        uint32_t bh0 = Bh[cur][k0][nb+g], bh1 = Bh[cur][k0+4][nb+g];
        uint32_t bl0 = Bl[cur][k0][nb+g], bl1 = Bl[cur][k0+4][nb+g];
#pragma unroll
        for (int mt = 0; mt < 2; mt++){
          MMA_TF32(acc[mt][nt], ah[mt][0], ah[mt][1], ah[mt][2], ah[mt][3], bl0, bl1);
          MMA_TF32(acc[mt][nt], al[mt][0], al[mt][1], al[mt][2], al[mt][3], bh0, bh1);
          MMA_TF32(acc[mt][nt], ah[mt][0], ah[mt][1], ah[mt][2], ah[mt][3], bh0, bh1);
        }
      }
    }
    // no trailing sync: next store targets the other buffer
  }

#pragma unroll
  for (int mt = 0; mt < 2; mt++){
    int m = m0 + wr*32 + mt*16 + g;
#pragma unroll
    for (int nt = 0; nt < 4; nt++){
      int cc = n0 + wn*32 + nt*8 + cq*2;
      *(float2*)&out[(size_t)m*HID + cc]     = make_float2(acc[mt][nt][0], acc[mt][nt][1]);
      *(float2*)&out[(size_t)(m+8)*HID + cc] = make_float2(acc[mt][nt][2], acc[mt][nt][3]);
    }
  }
}

// ------------------------- launcher -------------------------
extern "C" void kernel_launch(void* const* d_in, const int* in_sizes, int n_in,
                              void* d_out, int out_size){
  const float* x    = (const float*)d_in[0];
  const float* Wq   = (const float*)d_in[1];
  const float* Wk   = (const float*)d_in[2];
  const float* Wv   = (const float*)d_in[3];
  const float* Wa   = (const float*)d_in[4];
  const float* ba   = (const float*)d_in[5];
  const float* Wb   = (const float*)d_in[6];
  const float* bb   = (const float*)d_in[7];
  const float* lpar = (const float*)d_in[8];
  const float* onw  = (const float*)d_in[9];
  const float* Wo   = (const float*)d_in[10];
  float* out = (float*)d_out;

  cudaFuncSetAttribute(k_qkv, cudaFuncAttributeMaxDynamicSharedMemorySize, QKV_SMEM);
  cudaFuncSetAttribute(k_out, cudaFuncAttributeMaxDynamicSharedMemorySize, OUT_SMEM);

  k_qkv<<<dim3(16, 8, 4), 256, QKV_SMEM>>>(x, Wq, Wk, Wv, Wa, ba, Wb, bb);
  k_chunkscan<<<dim3(8, BH), 256>>>();
  k_solve<<<dim3(NC, BH), 256>>>(lpar, onw);
  k_out<<<dim3(16, 8), 256, OUT_SMEM>>>(Wo, out);
}

// round 16
// speedup vs baseline: 1.0816x; 1.0234x over previous
#include <cuda_runtime.h>
#include <math.h>
#include <stdint.h>

#define BN   2
#define TT   256
#define HID  2048
#define NOUT 2048
#define NH   16
#define HD   128
#define BH   32
#define CS   8
#define NC   32
#define NCG  6
#define MROWS (BN*TT)

typedef unsigned long long ull;

// dynamic smem layout (bytes) for the TF32 GEMM tiles, double-buffered
#define AH_OFF   0u          // uint32[2][64][20]  = 10240
#define AL_OFF   10240u      // uint32[2][64][20]  = 10240
#define BH_OFF   20480u      // uint32[2][16][136] = 17408
#define BL_OFF   37888u      // uint32[2][16][136] = 17408
#define L2S_OFF  55296u      // float[64][4]       = 1024
#define QKV_SMEM 56320u
#define OUT_SMEM 55296u

// ------------------------- scratch (device globals) -------------------------
__device__ float g_Q[BH*TT*HD];
__device__ float g_K[BH*TT*HD];
__device__ float g_V[BH*TT*HD];
__device__ float g_Of[MROWS*HID];
__device__ float g_g[BH*TT];
__device__ float g_beta[BH*TT];
__device__ float g_Skk[BH*NC*HD*HD];
__device__ float g_Skv[BH*NC*HD*HD];

// ------------------------- helpers -------------------------
__device__ __forceinline__ float warp_sum(float v){
#pragma unroll
  for (int o = 16; o; o >>= 1) v += __shfl_xor_sync(0xffffffffu, v, o);
  return v;
}
__device__ __forceinline__ ull bcast2(float x){
  ull r; asm("mov.b64 %0, {%1, %1};" : "=l"(r) : "f"(x)); return r;
}
__device__ __forceinline__ void ffma2(ull& d, ull a, ull b){
  asm("fma.rn.f32x2 %0, %1, %2, %0;" : "+l"(d) : "l"(a), "l"(b));
}
__device__ __forceinline__ float2 unpack2(ull v){
  float2 f; asm("mov.b64 {%0, %1}, %2;" : "=f"(f.x), "=f"(f.y) : "l"(v)); return f;
}
__device__ __forceinline__ float silu(float z){ return z / (1.f + expf(-z)); }
__device__ __forceinline__ void group_bar(int g){
  asm volatile("bar.sync %0, %1;" :: "r"(1 + g), "r"(128) : "memory");
}
__device__ __forceinline__ uint32_t f2tf32(float v){
  uint32_t r; asm("cvt.rna.tf32.f32 %0, %1;" : "=r"(r) : "f"(v)); return r;
}

#define MMA_TF32(d, a0,a1,a2,a3, b0,b1) \
  asm volatile("mma.sync.aligned.m16n8k8.row.col.f32.tf32.tf32.f32 " \
    "{%0,%1,%2,%3}, {%4,%5,%6,%7}, {%8,%9}, {%0,%1,%2,%3};" \
    : "+f"((d)[0]),"+f"((d)[1]),"+f"((d)[2]),"+f"((d)[3]) \
    : "r"(a0),"r"(a1),"r"(a2),"r"(a3), "r"(b0),"r"(b1))

// ------------------------- K1: QKV GEMM (3xTF32, dbl-buf dyn-smem) ------------
__global__ void __launch_bounds__(256,2) k_qkv(const float* __restrict__ X,
                                               const float* __restrict__ Wq,
                                               const float* __restrict__ Wk,
                                               const float* __restrict__ Wv,
                                               const float* __restrict__ Wa,
                                               const float* __restrict__ ba,
                                               const float* __restrict__ Wb,
                                               const float* __restrict__ bb){
  extern __shared__ __align__(16) char smem_raw[];
  int z = blockIdx.z;
  int tid = threadIdx.x;

  if (z == 3){
    // ---- gates path (reuses dynamic smem) ----
    float* xr = (float*)smem_raw;                   // [2048]
    float (*red)[32] = (float(*)[32])(smem_raw + 8192);
    int cta = blockIdx.y * 16 + blockIdx.x;         // 0..127
    for (int r4 = 0; r4 < 4; r4++){
      int row = cta*4 + r4;
      int b = row >> 8, t = row & 255;
      const float4* xp = (const float4*)(X + (size_t)row * HID);
      for (int idx = tid; idx < HID/4; idx += 256)
        *(float4*)&xr[idx*4] = xp[idx];
      __syncthreads();
      int o = tid & 31, k8 = tid >> 5;
      float partial = 0.f;
      if (o < 16){
        for (int cc = k8*256; cc < k8*256+256; cc++) partial += xr[cc] * Wa[cc*NH + o];
      } else {
        int oo = o - 16;
        for (int cc = k8*256; cc < k8*256+256; cc++) partial += xr[cc] * Wb[cc*NH + oo];
      }
      red[k8][o] = partial;
      __syncthreads();
      if (tid < 32){
        float v = 0.f;
#pragma unroll
        for (int u = 0; u < 8; u++) v += red[u][tid];
        if (tid < 16){
          float zz = v + ba[tid];
          float ls = (zz >= 0.f) ? -log1pf(expf(-zz)) : (zz - log1pf(expf(zz)));
          g_g[(b*NH + tid)*TT + t] = ls;
        } else {
          int hh = tid - 16;
          float zz = v + bb[hh];
          g_beta[(b*NH + hh)*TT + t] = 1.f / (1.f + expf(-zz));
        }
      }
      __syncthreads();
    }
    return;
  }

  uint32_t (*Ah)[64][20]  = (uint32_t(*)[64][20])(smem_raw + AH_OFF);
  uint32_t (*Al)[64][20]  = (uint32_t(*)[64][20])(smem_raw + AL_OFF);
  uint32_t (*Bh)[16][136] = (uint32_t(*)[16][136])(smem_raw + BH_OFF);
  uint32_t (*Bl)[16][136] = (uint32_t(*)[16][136])(smem_raw + BL_OFF);
  float (*l2s)[4]         = (float(*)[4])(smem_raw + L2S_OFF);

  const float* W = z == 0 ? Wq : (z == 1 ? Wk : Wv);
  float* DST     = z == 0 ? g_Q : (z == 1 ? g_K : g_V);

  int lane = tid & 31, warp = tid >> 5;
  int wr = warp >> 2, wn = warp & 3;
  int g = lane >> 2, cq = lane & 3;
  int m0 = blockIdx.y * 64;
  int h = blockIdx.x;
  int n0 = h * 128;

  float acc[2][4][4];
#pragma unroll
  for (int mt = 0; mt < 2; mt++)
#pragma unroll
    for (int nt = 0; nt < 4; nt++)
#pragma unroll
      for (int j = 0; j < 4; j++) acc[mt][nt][j] = 0.f;

  int am = tid >> 2, ak = (tid & 3) * 4;
  int bk0 = tid >> 5, bn0 = (tid & 31) * 4;
  float4 pa, pb[2];
  pa = *(const float4*)&X[(size_t)(m0 + am)*HID + ak];
#pragma unroll
  for (int p = 0; p < 2; p++)
    pb[p] = *(const float4*)&W[(size_t)(bk0 + p*8)*NOUT + n0 + bn0];

  for (int kb = 0; kb < HID; kb += 16){
    int cur = (kb >> 4) & 1;
    {
      float vv[4] = {pa.x, pa.y, pa.z, pa.w};
      uint32_t hi[4], lo[4];
#pragma unroll
      for (int e = 0; e < 4; e++){
        hi[e] = f2tf32(vv[e]);
        lo[e] = f2tf32(vv[e] - __uint_as_float(hi[e]));
      }
      *(uint4*)&Ah[cur][am][ak] = make_uint4(hi[0], hi[1], hi[2], hi[3]);
      *(uint4*)&Al[cur][am][ak] = make_uint4(lo[0], lo[1], lo[2], lo[3]);
#pragma unroll
      for (int p = 0; p < 2; p++){
        float wv[4] = {pb[p].x, pb[p].y, pb[p].z, pb[p].w};
#pragma unroll
        for (int e = 0; e < 4; e++){
          hi[e] = f2tf32(wv[e]);
          lo[e] = f2tf32(wv[e] - __uint_as_float(hi[e]));
        }
        *(uint4*)&Bh[cur][bk0 + p*8][bn0] = make_uint4(hi[0], hi[1], hi[2], hi[3]);
        *(uint4*)&Bl[cur][bk0 + p*8][bn0] = make_uint4(lo[0], lo[1], lo[2], lo[3]);
      }
    }
    __syncthreads();
    if (kb + 16 < HID){
      pa = *(const float4*)&X[(size_t)(m0 + am)*HID + kb + 16 + ak];
#pragma unroll
      for (int p = 0; p < 2; p++)
        pb[p] = *(const float4*)&W[(size_t)(kb + 16 + bk0 + p*8)*NOUT + n0 + bn0];
    }
#pragma unroll
    for (int ks = 0; ks < 2; ks++){
      int k0 = ks*8 + cq;
      uint32_t ah[2][4], al[2][4];
#pragma unroll
      for (int mt = 0; mt < 2; mt++){
        int mb = wr*32 + mt*16;
        ah[mt][0] = Ah[cur][mb+g][k0];   ah[mt][1] = Ah[cur][mb+g+8][k0];
        ah[mt][2] = Ah[cur][mb+g][k0+4]; ah[mt][3] = Ah[cur][mb+g+8][k0+4];
        al[mt][0] = Al[cur][mb+g][k0];   al[mt][1] = Al[cur][mb+g+8][k0];
        al[mt][2] = Al[cur][mb+g][k0+4]; al[mt][3] = Al[cur][mb+g+8][k0+4];
      }
#pragma unroll
      for (int nt = 0; nt < 4; nt++){
        int nb = wn*32 + nt*8;
        uint32_t bh0 = Bh[cur][k0][nb+g], bh1 = Bh[cur][k0+4][nb+g];
        uint32_t bl0 = Bl[cur][k0][nb+g], bl1 = Bl[cur][k0+4][nb+g];
#pragma unroll
        for (int mt = 0; mt < 2; mt++){
          MMA_TF32(acc[mt][nt], ah[mt][0], ah[mt][1], ah[mt][2], ah[mt][3], bl0, bl1);
          MMA_TF32(acc[mt][nt], al[mt][0], al[mt][1], al[mt][2], al[mt][3], bh0, bh1);
          MMA_TF32(acc[mt][nt], ah[mt][0], ah[mt][1], ah[mt][2], ah[mt][3], bh0, bh1);
        }
      }
    }
    // no trailing sync: next store targets the other buffer
  }

  float v[2][4][4];
#pragma unroll
  for (int mt = 0; mt < 2; mt++)
#pragma unroll
    for (int nt = 0; nt < 4; nt++)
#pragma unroll
      for (int j = 0; j < 4; j++) v[mt][nt][j] = silu(acc[mt][nt][j]);

  float scale[2][2] = {{1.f,1.f},{1.f,1.f}};
  if (z < 2){
#pragma unroll
    for (int mt = 0; mt < 2; mt++){
      float s0 = 0.f, s1 = 0.f;
#pragma unroll
      for (int nt = 0; nt < 4; nt++){
        s0 += v[mt][nt][0]*v[mt][nt][0] + v[mt][nt][1]*v[mt][nt][1];
        s1 += v[mt][nt][2]*v[mt][nt][2] + v[mt][nt][3]*v[mt][nt][3];
      }
      s0 += __shfl_xor_sync(0xffffffffu, s0, 1);
      s0 += __shfl_xor_sync(0xffffffffu, s0, 2);
      s1 += __shfl_xor_sync(0xffffffffu, s1, 1);
      s1 += __shfl_xor_sync(0xffffffffu, s1, 2);
      if (cq == 0){
        l2s[wr*32 + mt*16 + g][wn]     = s0;
        l2s[wr*32 + mt*16 + g + 8][wn] = s1;
      }
    }
    __syncthreads();
#pragma unroll
    for (int mt = 0; mt < 2; mt++){
      float4 q0 = *(const float4*)&l2s[wr*32 + mt*16 + g][0];
      float4 q1 = *(const float4*)&l2s[wr*32 + mt*16 + g + 8][0];
      float s0 = (q0.x + q0.y) + (q0.z + q0.w);
      float s1 = (q1.x + q1.y) + (q1.z + q1.w);
      scale[mt][0] = 1.f / fmaxf(sqrtf(s0), 1e-12f);
      scale[mt][1] = 1.f / fmaxf(sqrtf(s1), 1e-12f);
    }
  }

#pragma unroll
  for (int mt = 0; mt < 2; mt++){
    int m = m0 + wr*32 + mt*16 + g;
    int b = m >> 8, t = m & 255;
#pragma unroll
    for (int nt = 0; nt < 4; nt++){
      int d = wn*32 + nt*8 + cq*2;
      size_t off = ((size_t)((b*NH + h)*TT + t))*HD + d;
      *(float2*)&DST[off] = make_float2(v[mt][nt][0]*scale[mt][0],
                                        v[mt][nt][1]*scale[mt][0]);
      *(float2*)&DST[off + 8*HD] = make_float2(v[mt][nt][2]*scale[mt][1],
                                               v[mt][nt][3]*scale[mt][1]);
    }
  }
}

// ------------------------- K2: chunk sums + scan fused ------------------------
__global__ void __launch_bounds__(256,4) k_chunkscan(){
  int vslab = blockIdx.x, bh = blockIdx.y;
  int tid = threadIdx.x;
  int i  = vslab*16 + (tid >> 4);
  int j0 = (tid & 15) * 8;
  __shared__ __align__(16) float ks[CS][HD], vs[CS][HD];
  __shared__ float coef[CS];
  __shared__ float dcs;
  float ckk[8], ckv[8];
#pragma unroll
  for (int u = 0; u < 8; u++){ ckk[u] = 0.f; ckv[u] = 0.f; }

  for (int c = 0; c < NC; c++){
    if (c) __syncthreads();
    {
      const float4* Kp = (const float4*)(g_K + (size_t)(bh*TT + c*CS)*HD);
      const float4* Vp = (const float4*)(g_V + (size_t)(bh*TT + c*CS)*HD);
      ((float4*)ks)[tid] = Kp[tid];
      ((float4*)vs)[tid] = Vp[tid];
    }
    if (tid < CS){
      float s = 0.f;
      for (int u = tid + 1; u < CS; u++) s += g_g[bh*TT + c*CS + u];
      coef[tid] = g_beta[bh*TT + c*CS + tid] * expf(s);
    }
    if (tid == 8){
      float s = 0.f;
      for (int u = 0; u < CS; u++) s += g_g[bh*TT + c*CS + u];
      dcs = expf(s);
    }
    __syncthreads();
    float dc = dcs;
#pragma unroll
    for (int u = 0; u < 8; u++){ ckk[u] *= dc; ckv[u] *= dc; }
#pragma unroll
    for (int s = 0; s < CS; s++){
      float ki = ks[s][i] * coef[s];
      float4 ka = *(const float4*)&ks[s][j0];
      float4 kb = *(const float4*)&ks[s][j0+4];
      float4 va = *(const float4*)&vs[s][j0];
      float4 vb = *(const float4*)&vs[s][j0+4];
      ckk[0] += ki*ka.x; ckk[1] += ki*ka.y; ckk[2] += ki*ka.z; ckk[3] += ki*ka.w;
      ckk[4] += ki*kb.x; ckk[5] += ki*kb.y; ckk[6] += ki*kb.z; ckk[7] += ki*kb.w;
      ckv[0] += ki*va.x; ckv[1] += ki*va.y; ckv[2] += ki*va.z; ckv[3] += ki*va.w;
      ckv[4] += ki*vb.x; ckv[5] += ki*vb.y; ckv[6] += ki*vb.z; ckv[7] += ki*vb.w;
    }
    size_t base = ((size_t)(bh*NC + c) << 14) + (size_t)i*HD + j0;
    *(float4*)&g_Skk[base]   = make_float4(ckk[0], ckk[1], ckk[2], ckk[3]);
    *(float4*)&g_Skk[base+4] = make_float4(ckk[4], ckk[5], ckk[6], ckk[7]);
    *(float4*)&g_Skv[base]   = make_float4(ckv[0], ckv[1], ckv[2], ckv[3]);
    *(float4*)&g_Skv[base+4] = make_float4(ckv[4], ckv[5], ckv[6], ckv[7]);
  }
}

// ------------------------- K3: batched 8-RHS CG solve (256 thr, 2 CTAs/SM) ----
#define PHASE_A(MSM) do { \
  ull y0a=0ull, y0b=0ull, y0c=0ull, y0d=0ull; \
  ull y1a=0ull, y1b=0ull, y1c=0ull, y1d=0ull; \
  _Pragma("unroll") \
  for (int jj = 0; jj < 32; jj++){ \
    ulonglong2 pA = *(const ulonglong2*)&P[mq*32+jj][0]; \
    ulonglong2 pB = *(const ulonglong2*)&P[mq*32+jj][4]; \
    ull h0 = bcast2(hk[jj]); \
    ull h1 = bcast2(hk[32+jj]); \
    ffma2(y0a, h0, pA.x); ffma2(y0b, h0, pA.y); ffma2(y0c, h0, pB.x); ffma2(y0d, h0, pB.y); \
    ffma2(y1a, h1, pA.x); ffma2(y1b, h1, pA.y); ffma2(y1c, h1, pB.x); ffma2(y1d, h1, pB.y); \
  } \
  *(ulonglong2*)&part[mq][mi][0] = make_ulonglong2(y0a, y0b); \
  *(ulonglong2*)&part[mq][mi][4] = make_ulonglong2(y0c, y0d); \
  *(ulonglong2*)&part[mq][mi+64][0] = make_ulonglong2(y1a, y1b); \
  *(ulonglong2*)&part[mq][mi+64][4] = make_ulonglong2(y1c, y1d); \
  { float4 kv_ = *(const float4*)&MSM[warp][lane*4]; \
    _Pragma("unroll") \
    for (int t_ = 0; t_ < 8; t_++){ \
      float4 pv_ = *(const float4*)&PT[t_][lane*4]; \
      float pd_ = kv_.x*pv_.x + kv_.y*pv_.y + kv_.z*pv_.z + kv_.w*pv_.w; \
      pd_ = warp_sum(pd_); \
      if (lane == 0) dots[t_][warp] = pd_; \
    } } \
} while(0)

#define ASM4(OUT) do { \
  float4 ya_ = make_float4(0.f, 0.f, 0.f, 0.f); \
  _Pragma("unroll") \
  for (int q2 = 0; q2 < 4; q2++){ \
    float4 pr_ = *(const float4*)&part[q2][si][t0]; \
    ya_.x += pr_.x; ya_.y += pr_.y; ya_.z += pr_.z; ya_.w += pr_.w; \
  } \
  float yarr_[4] = {ya_.x, ya_.y, ya_.z, ya_.w}; \
  _Pragma("unroll") \
  for (int u = 0; u < 4; u++){ \
    int t_ = t0 + u; \
    float a_ = cdec[t_] * yarr_[u]; \
    float4 d0_ = *(const float4*)&dots[t_][0]; \
    float4 d1_ = *(const float4*)&dots[t_][4]; \
    float4 w0_ = *(const float4*)&Wc[t_][0]; \
    float4 w1_ = *(const float4*)&Wc[t_][4]; \
    a_ += (w0_.x*d0_.x)*ksi[0] + (w0_.y*d0_.y)*ksi[1] \
        + (w0_.z*d0_.z)*ksi[2] + (w0_.w*d0_.w)*ksi[3] \
        + (w1_.x*d1_.x)*ksi[4] + (w1_.y*d1_.y)*ksi[5] \
        + (w1_.z*d1_.z)*ksi[6] + (w1_.w*d1_.w)*ksi[7]; \
    OUT[u] = a_; \
  } \
} while(0)

__global__ void __launch_bounds__(256,2) k_solve(const float* __restrict__ lp,
                                                 const float* __restrict__ onw){
  int c = blockIdx.x, bh = blockIdx.y;
  int b = bh >> 4, h = bh & 15;
  int tid = threadIdx.x;
  int si = tid & 127, sg2 = tid >> 7, lane = tid & 31, warp = tid >> 5;
  int mi = tid & 63, mq = tid >> 6;
  int g0 = bh*TT + c*CS;
  int t0 = sg2*4;

  __shared__ __align__(16) float Ksm[CS][HD], Vsm[CS][HD], Qsm[CS][HD];
  __shared__ __align__(16) float P[HD][12];
  __shared__ __align__(16) float PT[CS][HD+4];
  __shared__ __align__(16) float part[4][HD][12];
  __shared__ __align__(16) float dots[CS][CS];
  __shared__ __align__(16) float Wc[CS][CS];
  __shared__ float cdec[CS];
  __shared__ float lam[HD], dg[HD], gsm[CS], bsm[CS];
  __shared__ __align__(16) float wredA[4][8];
  __shared__ __align__(16) float wredB[4][8];

  {
    const float4* Kp = (const float4*)(g_K + (size_t)g0*HD);
    const float4* Vp = (const float4*)(g_V + (size_t)g0*HD);
    const float4* Qp = (const float4*)(g_Q + (size_t)g0*HD);
    ((float4*)Ksm)[tid] = Kp[tid];
    ((float4*)Qsm)[tid] = Qp[tid];
    ((float4*)Vsm)[tid] = Vp[tid];
  }
  if (tid >= 128 && tid < 136){ gsm[tid-128] = g_g[g0 + tid-128]; bsm[tid-128] = g_beta[g0 + tid-128]; }
  if (tid < 128){
    float zz = lp[h*HD + tid];
    float sp = (zz > 20.f) ? zz : log1pf(expf(zz));
    lam[tid] = sp + 0.25f;
  }
  float hk[64];
  if (c == 0){
#pragma unroll
    for (int jj = 0; jj < 64; jj++) hk[jj] = 0.f;
  } else {
    size_t base = ((size_t)(bh*NC + (c-1)) << 14) + mq*32;
#pragma unroll
    for (int jj = 0; jj < 32; jj += 4){
      float4 a = *(const float4*)&g_Skk[base + (size_t)mi*HD + jj];
      hk[jj] = a.x; hk[jj+1] = a.y; hk[jj+2] = a.z; hk[jj+3] = a.w;
      float4 a2 = *(const float4*)&g_Skk[base + (size_t)(mi+64)*HD + jj];
      hk[32+jj] = a2.x; hk[33+jj] = a2.y; hk[34+jj] = a2.z; hk[35+jj] = a2.w;
    }
  }
  if (mq == (mi >> 5))       dg[mi]      = hk[mi & 31];
  if (mq == 2 + (mi >> 5))   dg[mi + 64] = hk[32 + (mi & 31)];
  __syncthreads();

  if (tid < 64){
    int t_ = tid >> 3, s_ = tid & 7;
    float w = 0.f;
    if (s_ <= t_){
      float s = 0.f;
      for (int u = s_+1; u <= t_; u++) s += gsm[u];
      w = bsm[s_] * expf(s);
    }
    Wc[t_][s_] = w;
  }
  if (tid >= 64 && tid < 72){
    int t_ = tid - 64;
    float s = 0.f;
    for (int u = 0; u <= t_; u++) s += gsm[u];
    cdec[t_] = expf(s);
  }
  __syncthreads();

  float ksi[CS];
#pragma unroll
  for (int s = 0; s < CS; s++) ksi[s] = Ksm[s][si];
  float xv[4], rv[4], pv[4], dloc[4], qv[4];
  unsigned dmask = 0;
#pragma unroll
  for (int u = 0; u < 4; u++){
    int t = t0 + u;
    float diag = cdec[t]*dg[si] + lam[si];
#pragma unroll
    for (int s = 0; s < CS; s++) diag += Wc[t][s] * ksi[s] * ksi[s];
    float x = Qsm[t][si] / (diag + 1e-8f);
    xv[u] = x; P[si][t] = x; PT[t][si] = x;
  }
  __syncthreads();

  PHASE_A(Ksm);
  __syncthreads();
  {
    float av[4];
    ASM4(av);
#pragma unroll
    for (int u = 0; u < 4; u++){
      int t = t0 + u;
      float r = Qsm[t][si] - (av[u] + lam[si]*xv[u]);
      rv[u] = r; pv[u] = r;
      float rr = warp_sum(r*r);
      if (lane == 0) wredA[u][warp] = rr;
      P[si][t] = r; PT[t][si] = r;
    }
  }
  group_bar(sg2);
#pragma unroll
  for (int u = 0; u < 4; u++){
    float4 wv = *(const float4*)&wredA[u][sg2*4];
    dloc[u] = (wv.x + wv.y) + (wv.z + wv.w);
  }
  __syncthreads();

  for (int it = 0; it < NCG; it++){
    PHASE_A(Ksm);
    __syncthreads();
    {
      ASM4(qv);
#pragma unroll
      for (int u = 0; u < 4; u++){
        qv[u] += lam[si] * pv[u];
        float pq = warp_sum(pv[u] * qv[u]);
        if (lane == 0) wredA[u][warp] = pq;
      }
    }
    group_bar(sg2);
#pragma unroll
    for (int u = 0; u < 4; u++){
      float4 wv = *(const float4*)&wredA[u][sg2*4];
      float pq = (wv.x + wv.y) + (wv.z + wv.w);
      if (dloc[u] < 1e-10f) dmask |= 1u << u;
      if (fabsf(pq) < 1e-10f) dmask |= 1u << u;
      float alpha = (dmask >> u & 1u) ? 0.f : dloc[u] / pq;
      xv[u] += alpha * pv[u];
      rv[u] -= alpha * qv[u];
      float rr = warp_sum(rv[u] * rv[u]);
      if (lane == 0) wredB[u][warp] = rr;
    }
    group_bar(sg2);
#pragma unroll
    for (int u = 0; u < 4; u++){
      int t = t0 + u;
      float4 wv = *(const float4*)&wredB[u][sg2*4];
      float dn = (wv.x + wv.y) + (wv.z + wv.w);
      if (!(dmask >> u & 1u)){
        float bet = dn / dloc[u];
        dloc[u] = dn;
        pv[u] = rv[u] + bet * pv[u];
      }
      P[si][t] = pv[u]; PT[t][si] = pv[u];
    }
    __syncthreads();
  }

#pragma unroll
  for (int u = 0; u < 4; u++){
    int t = t0 + u;
    P[si][t] = xv[u]; PT[t][si] = xv[u];
  }
  if (c == 0){
#pragma unroll
    for (int jj = 0; jj < 64; jj++) hk[jj] = 0.f;
  } else {
    size_t base = ((size_t)(bh*NC + (c-1)) << 14) + mq*32;
#pragma unroll
    for (int jj = 0; jj < 32; jj += 4){
      float4 a = *(const float4*)&g_Skv[base + (size_t)mi*HD + jj];
      hk[jj] = a.x; hk[jj+1] = a.y; hk[jj+2] = a.z; hk[jj+3] = a.w;
      float4 a2 = *(const float4*)&g_Skv[base + (size_t)(mi+64)*HD + jj];
      hk[32+jj] = a2.x; hk[33+jj] = a2.y; hk[34+jj] = a2.z; hk[35+jj] = a2.w;
    }
  }
  __syncthreads();
  PHASE_A(Vsm);
  __syncthreads();
  float ov[4];
  ASM4(ov);
#pragma unroll
  for (int u = 0; u < 4; u++){
    float ss = warp_sum(ov[u]*ov[u]);
    if (lane == 0) wredA[u][warp] = ss;
  }
  group_bar(sg2);
  float wnv = onw[si];
#pragma unroll
  for (int u = 0; u < 4; u++){
    int t = t0 + u;
    float4 wv = *(const float4*)&wredA[u][sg2*4];
    float ms = ((wv.x + wv.y) + (wv.z + wv.w)) * (1.f/128.f);
    float rms = sqrtf(ms + 1e-6f);
    int ts = c*CS + t;
    g_Of[(size_t)(b*TT + ts)*HID + h*HD + si] = ov[u] / rms * wnv;
  }
}

// ------------------------- K4: output projection (3xTF32, dbl-buf dyn-smem) ---
__global__ void __launch_bounds__(256) k_out(const float* __restrict__ Wo,
                                             float* __restrict__ out){
  extern __shared__ __align__(16) char smem_raw[];
  uint32_t (*Ah)[64][20]  = (uint32_t(*)[64][20])(smem_raw + AH_OFF);
  uint32_t (*Al)[64][20]  = (uint32_t(*)[64][20])(smem_raw + AL_OFF);
  uint32_t (*Bh)[16][136] = (uint32_t(*)[16][136])(smem_raw + BH_OFF);
  uint32_t (*Bl)[16][136] = (uint32_t(*)[16][136])(smem_raw + BL_OFF);

  int tid = threadIdx.x;
  int lane = tid & 31, warp = tid >> 5;
  int wr = warp >> 2, wn = warp & 3;
  int g = lane >> 2, cq = lane & 3;
  int m0 = blockIdx.y * 64;
  int n0 = blockIdx.x * 128;

  float acc[2][4][4];
#pragma unroll
  for (int mt = 0; mt < 2; mt++)
#pragma unroll
    for (int nt = 0; nt < 4; nt++)
#pragma unroll
      for (int j = 0; j < 4; j++) acc[mt][nt][j] = 0.f;

  int am = tid >> 2, ak = (tid & 3) * 4;
  int bk0 = tid >> 5, bn0 = (tid & 31) * 4;
  float4 pa, pb[2];
  pa = *(const float4*)&g_Of[(size_t)(m0 + am)*HID + ak];
#pragma unroll
  for (int p = 0; p < 2; p++)
    pb[p] = *(const float4*)&Wo[(size_t)(bk0 + p*8)*HID + n0 + bn0];

  for (int kb = 0; kb < HID; kb += 16){
    int cur = (kb >> 4) & 1;
    {
      float vv[4] = {pa.x, pa.y, pa.z, pa.w};
      uint32_t hi[4], lo[4];
#pragma unroll
      for (int e = 0; e < 4; e++){
        hi[e] = f2tf32(vv[e]);
        lo[e] = f2tf32(vv[e] - __uint_as_float(hi[e]));
      }
      *(uint4*)&Ah[cur][am][ak] = make_uint4(hi[0], hi[1], hi[2], hi[3]);
      *(uint4*)&Al[cur][am][ak] = make_uint4(lo[0], lo[1], lo[2], lo[3]);
#pragma unroll
      for (int p = 0; p < 2; p++){
        float wv[4] = {pb[p].x, pb[p].y, pb[p].z, pb[p].w};
#pragma unroll
        for (int e = 0; e < 4; e++){
          hi[e] = f2tf32(wv[e]);
          lo[e] = f2tf32(wv[e] - __uint_as_float(hi[e]));
        }
        *(uint4*)&Bh[cur][bk0 + p*8][bn0] = make_uint4(hi[0], hi[1], hi[2], hi[3]);
        *(uint4*)&Bl[cur][bk0 + p*8][bn0] = make_uint4(lo[0], lo[1], lo[2], lo[3]);
      }
    }
    __syncthreads();
    if (kb + 16 < HID){
      pa = *(const float4*)&g_Of[(size_t)(m0 + am)*HID + kb + 16 + ak];
#pragma unroll
      for (int p = 0; p < 2; p++)
        pb[p] = *(const float4*)&Wo[(size_t)(kb + 16 + bk0 + p*8)*HID + n0 + bn0];
    }
#pragma unroll
    for (int ks = 0; ks < 2; ks++){
      int k0 = ks*8 + cq;
      uint32_t ah[2][4], al[2][4];
#pragma unroll
      for (int mt = 0; mt < 2; mt++){
        int mb = wr*32 + mt*16;
        ah[mt][0] = Ah[cur][mb+g][k0];   ah[mt][1] = Ah[cur][mb+g+8][k0];
        ah[mt][2] = Ah[cur][mb+g][k0+4]; ah[mt][3] = Ah[cur][mb+g+8][k0+4];
        al[mt][0] = Al[cur][mb+g][k0];   al[mt][1] = Al[cur][mb+g+8][k0];
        al[mt][2] = Al[cur][mb+g][k0+4]; al[mt][3] = Al[cur][mb+g+8][k0+4];
      }
#pragma unroll
      for (int nt = 0; nt < 4; nt++){
        int nb = wn*32 + nt*8;
        uint32_t bh0 = Bh[cur][k0][nb+g], bh1 = Bh[cur][k0+4][nb+g];
        uint32_t bl0 = Bl[cur][k0][nb+g], bl1 = Bl[cur][k0+4][nb+g];
#pragma unroll
        for (int mt = 0; mt < 2; mt++){
          MMA_TF32(acc[mt][nt], ah[mt][0], ah[mt][1], ah[mt][2], ah[mt][3], bl0, bl1);
          MMA_TF32(acc[mt][nt], al[mt][0], al[mt][1], al[mt][2], al[mt][3], bh0, bh1);
          MMA_TF32(acc[mt][nt], ah[mt][0], ah[mt][1], ah[mt][2], ah[mt][3], bh0, bh1);
        }
      }
    }
    // no trailing sync: next store targets the other buffer
  }

#pragma unroll
  for (int mt = 0; mt < 2; mt++){
    int m = m0 + wr*32 + mt*16 + g;
#pragma unroll
    for (int nt = 0; nt < 4; nt++){
      int cc = n0 + wn*32 + nt*8 + cq*2;
      *(float2*)&out[(size_t)m*HID + cc]     = make_float2(acc[mt][nt][0], acc[mt][nt][1]);
      *(float2*)&out[(size_t)(m+8)*HID + cc] = make_float2(acc[mt][nt][2], acc[mt][nt][3]);
    }
  }
}

// ------------------------- launcher -------------------------
extern "C" void kernel_launch(void* const* d_in, const int* in_sizes, int n_in,
                              void* d_out, int out_size){
  const float* x    = (const float*)d_in[0];
  const float* Wq   = (const float*)d_in[1];
  const float* Wk   = (const float*)d_in[2];
  const float* Wv   = (const float*)d_in[3];
  const float* Wa   = (const float*)d_in[4];
  const float* ba   = (const float*)d_in[5];
  const float* Wb   = (const float*)d_in[6];
  const float* bb   = (const float*)d_in[7];
  const float* lpar = (const float*)d_in[8];
  const float* onw  = (const float*)d_in[9];
  const float* Wo   = (const float*)d_in[10];
  float* out = (float*)d_out;

  cudaFuncSetAttribute(k_qkv, cudaFuncAttributeMaxDynamicSharedMemorySize, QKV_SMEM);
  cudaFuncSetAttribute(k_out, cudaFuncAttributeMaxDynamicSharedMemorySize, OUT_SMEM);

  k_qkv<<<dim3(16, 8, 4), 256, QKV_SMEM>>>(x, Wq, Wk, Wv, Wa, ba, Wb, bb);
  k_chunkscan<<<dim3(8, BH), 256>>>();
  k_solve<<<dim3(NC, BH), 256>>>(lpar, onw);
  k_out<<<dim3(16, 8), 256, OUT_SMEM>>>(Wo, out);
}

// round 17
// speedup vs baseline: 1.1052x; 1.0218x over previous
#include <cuda_runtime.h>
#include <math.h>
#include <stdint.h>

#define BN   2
#define TT   256
#define HID  2048
#define NOUT 2048
#define NH   16
#define HD   128
#define BH   32
#define CS   8
#define NC   32
#define NCG  5
#define MROWS (BN*TT)

typedef unsigned long long ull;

// dynamic smem layout (bytes) for the TF32 GEMM tiles, double-buffered
#define AH_OFF   0u          // uint32[2][64][20]  = 10240
#define AL_OFF   10240u      // uint32[2][64][20]  = 10240
#define BH_OFF   20480u      // uint32[2][16][136] = 17408
#define BL_OFF   37888u      // uint32[2][16][136] = 17408
#define L2S_OFF  55296u      // float[64][4]       = 1024
#define QKV_SMEM 56320u
#define OUT_SMEM 55296u

// ------------------------- scratch (device globals) -------------------------
__device__ float g_Q[BH*TT*HD];
__device__ float g_K[BH*TT*HD];
__device__ float g_V[BH*TT*HD];
__device__ float g_Of[MROWS*HID];
__device__ float g_g[BH*TT];
__device__ float g_beta[BH*TT];
__device__ float g_Skk[BH*NC*HD*HD];
__device__ float g_Skv[BH*NC*HD*HD];

// ------------------------- helpers -------------------------
__device__ __forceinline__ float warp_sum(float v){
#pragma unroll
  for (int o = 16; o; o >>= 1) v += __shfl_xor_sync(0xffffffffu, v, o);
  return v;
}
__device__ __forceinline__ ull bcast2(float x){
  ull r; asm("mov.b64 %0, {%1, %1};" : "=l"(r) : "f"(x)); return r;
}
__device__ __forceinline__ void ffma2(ull& d, ull a, ull b){
  asm("fma.rn.f32x2 %0, %1, %2, %0;" : "+l"(d) : "l"(a), "l"(b));
}
__device__ __forceinline__ float2 unpack2(ull v){
  float2 f; asm("mov.b64 {%0, %1}, %2;" : "=f"(f.x), "=f"(f.y) : "l"(v)); return f;
}
__device__ __forceinline__ float silu(float z){ return z / (1.f + expf(-z)); }
__device__ __forceinline__ void group_bar(int g){
  asm volatile("bar.sync %0, %1;" :: "r"(1 + g), "r"(128) : "memory");
}
__device__ __forceinline__ uint32_t f2tf32(float v){
  uint32_t r; asm("cvt.rna.tf32.f32 %0, %1;" : "=r"(r) : "f"(v)); return r;
}

#define MMA_TF32(d, a0,a1,a2,a3, b0,b1) \
  asm volatile("mma.sync.aligned.m16n8k8.row.col.f32.tf32.tf32.f32 " \
    "{%0,%1,%2,%3}, {%4,%5,%6,%7}, {%8,%9}, {%0,%1,%2,%3};" \
    : "+f"((d)[0]),"+f"((d)[1]),"+f"((d)[2]),"+f"((d)[3]) \
    : "r"(a0),"r"(a1),"r"(a2),"r"(a3), "r"(b0),"r"(b1))

// ------------------------- K1: QKV GEMM (3xTF32, dbl-buf dyn-smem) ------------
__global__ void __launch_bounds__(256,2) k_qkv(const float* __restrict__ X,
                                               const float* __restrict__ Wq,
                                               const float* __restrict__ Wk,
                                               const float* __restrict__ Wv,
                                               const float* __restrict__ Wa,
                                               const float* __restrict__ ba,
                                               const float* __restrict__ Wb,
                                               const float* __restrict__ bb){
  extern __shared__ __align__(16) char smem_raw[];
  int z = blockIdx.z;
  int tid = threadIdx.x;

  if (z == 3){
    // ---- gates path (reuses dynamic smem) ----
    float* xr = (float*)smem_raw;                   // [2048]
    float (*red)[32] = (float(*)[32])(smem_raw + 8192);
    int cta = blockIdx.y * 16 + blockIdx.x;         // 0..127
    for (int r4 = 0; r4 < 4; r4++){
      int row = cta*4 + r4;
      int b = row >> 8, t = row & 255;
      const float4* xp = (const float4*)(X + (size_t)row * HID);
      for (int idx = tid; idx < HID/4; idx += 256)
        *(float4*)&xr[idx*4] = xp[idx];
      __syncthreads();
      int o = tid & 31, k8 = tid >> 5;
      float partial = 0.f;
      if (o < 16){
        for (int cc = k8*256; cc < k8*256+256; cc++) partial += xr[cc] * Wa[cc*NH + o];
      } else {
        int oo = o - 16;
        for (int cc = k8*256; cc < k8*256+256; cc++) partial += xr[cc] * Wb[cc*NH + oo];
      }
      red[k8][o] = partial;
      __syncthreads();
      if (tid < 32){
        float v = 0.f;
#pragma unroll
        for (int u = 0; u < 8; u++) v += red[u][tid];
        if (tid < 16){
          float zz = v + ba[tid];
          float ls = (zz >= 0.f) ? -log1pf(expf(-zz)) : (zz - log1pf(expf(zz)));
          g_g[(b*NH + tid)*TT + t] = ls;
        } else {
          int hh = tid - 16;
          float zz = v + bb[hh];
          g_beta[(b*NH + hh)*TT + t] = 1.f / (1.f + expf(-zz));
        }
      }
      __syncthreads();
    }
    return;
  }

  uint32_t (*Ah)[64][20]  = (uint32_t(*)[64][20])(smem_raw + AH_OFF);
  uint32_t (*Al)[64][20]  = (uint32_t(*)[64][20])(smem_raw + AL_OFF);
  uint32_t (*Bh)[16][136] = (uint32_t(*)[16][136])(smem_raw + BH_OFF);
  uint32_t (*Bl)[16][136] = (uint32_t(*)[16][136])(smem_raw + BL_OFF);
  float (*l2s)[4]         = (float(*)[4])(smem_raw + L2S_OFF);

  const float* W = z == 0 ? Wq : (z == 1 ? Wk : Wv);
  float* DST     = z == 0 ? g_Q : (z == 1 ? g_K : g_V);

  int lane = tid & 31, warp = tid >> 5;
  int wr = warp >> 2, wn = warp & 3;
  int g = lane >> 2, cq = lane & 3;
  int m0 = blockIdx.y * 64;
  int h = blockIdx.x;
  int n0 = h * 128;

  float acc[2][4][4];
#pragma unroll
  for (int mt = 0; mt < 2; mt++)
#pragma unroll
    for (int nt = 0; nt < 4; nt++)
#pragma unroll
      for (int j = 0; j < 4; j++) acc[mt][nt][j] = 0.f;

  int am = tid >> 2, ak = (tid & 3) * 4;
  int bk0 = tid >> 5, bn0 = (tid & 31) * 4;
  float4 pa, pb[2];
  pa = *(const float4*)&X[(size_t)(m0 + am)*HID + ak];
#pragma unroll
  for (int p = 0; p < 2; p++)
    pb[p] = *(const float4*)&W[(size_t)(bk0 + p*8)*NOUT + n0 + bn0];

  for (int kb = 0; kb < HID; kb += 16){
    int cur = (kb >> 4) & 1;
    {
      float vv[4] = {pa.x, pa.y, pa.z, pa.w};
      uint32_t hi[4], lo[4];
#pragma unroll
      for (int e = 0; e < 4; e++){
        hi[e] = f2tf32(vv[e]);
        lo[e] = f2tf32(vv[e] - __uint_as_float(hi[e]));
      }
      *(uint4*)&Ah[cur][am][ak] = make_uint4(hi[0], hi[1], hi[2], hi[3]);
      *(uint4*)&Al[cur][am][ak] = make_uint4(lo[0], lo[1], lo[2], lo[3]);
#pragma unroll
      for (int p = 0; p < 2; p++){
        float wv[4] = {pb[p].x, pb[p].y, pb[p].z, pb[p].w};
#pragma unroll
        for (int e = 0; e < 4; e++){
          hi[e] = f2tf32(wv[e]);
          lo[e] = f2tf32(wv[e] - __uint_as_float(hi[e]));
        }
        *(uint4*)&Bh[cur][bk0 + p*8][bn0] = make_uint4(hi[0], hi[1], hi[2], hi[3]);
        *(uint4*)&Bl[cur][bk0 + p*8][bn0] = make_uint4(lo[0], lo[1], lo[2], lo[3]);
      }
    }
    __syncthreads();
    if (kb + 16 < HID){
      pa = *(const float4*)&X[(size_t)(m0 + am)*HID + kb + 16 + ak];
#pragma unroll
      for (int p = 0; p < 2; p++)
        pb[p] = *(const float4*)&W[(size_t)(kb + 16 + bk0 + p*8)*NOUT + n0 + bn0];
    }
#pragma unroll
    for (int ks = 0; ks < 2; ks++){
      int k0 = ks*8 + cq;
      uint32_t ah[2][4], al[2][4];
#pragma unroll
      for (int mt = 0; mt < 2; mt++){
        int mb = wr*32 + mt*16;
        ah[mt][0] = Ah[cur][mb+g][k0];   ah[mt][1] = Ah[cur][mb+g+8][k0];
        ah[mt][2] = Ah[cur][mb+g][k0+4]; ah[mt][3] = Ah[cur][mb+g+8][k0+4];
        al[mt][0] = Al[cur][mb+g][k0];   al[mt][1] = Al[cur][mb+g+8][k0];
        al[mt][2] = Al[cur][mb+g][k0+4]; al[mt][3] = Al[cur][mb+g+8][k0+4];
      }
#pragma unroll
      for (int nt = 0; nt < 4; nt++){
        int nb = wn*32 + nt*8;
        uint32_t bh0 = Bh[cur][k0][nb+g], bh1 = Bh[cur][k0+4][nb+g];
        uint32_t bl0 = Bl[cur][k0][nb+g], bl1 = Bl[cur][k0+4][nb+g];
#pragma unroll
        for (int mt = 0; mt < 2; mt++){
          MMA_TF32(acc[mt][nt], ah[mt][0], ah[mt][1], ah[mt][2], ah[mt][3], bl0, bl1);
          MMA_TF32(acc[mt][nt], al[mt][0], al[mt][1], al[mt][2], al[mt][3], bh0, bh1);
          MMA_TF32(acc[mt][nt], ah[mt][0], ah[mt][1], ah[mt][2], ah[mt][3], bh0, bh1);
        }
      }
    }
    // no trailing sync: next store targets the other buffer
  }

  float v[2][4][4];
#pragma unroll
  for (int mt = 0; mt < 2; mt++)
#pragma unroll
    for (int nt = 0; nt < 4; nt++)
#pragma unroll
      for (int j = 0; j < 4; j++) v[mt][nt][j] = silu(acc[mt][nt][j]);

  float scale[2][2] = {{1.f,1.f},{1.f,1.f}};
  if (z < 2){
#pragma unroll
    for (int mt = 0; mt < 2; mt++){
      float s0 = 0.f, s1 = 0.f;
#pragma unroll
      for (int nt = 0; nt < 4; nt++){
        s0 += v[mt][nt][0]*v[mt][nt][0] + v[mt][nt][1]*v[mt][nt][1];
        s1 += v[mt][nt][2]*v[mt][nt][2] + v[mt][nt][3]*v[mt][nt][3];
      }
      s0 += __shfl_xor_sync(0xffffffffu, s0, 1);
      s0 += __shfl_xor_sync(0xffffffffu, s0, 2);
      s1 += __shfl_xor_sync(0xffffffffu, s1, 1);
      s1 += __shfl_xor_sync(0xffffffffu, s1, 2);
      if (cq == 0){
        l2s[wr*32 + mt*16 + g][wn]     = s0;
        l2s[wr*32 + mt*16 + g + 8][wn] = s1;
      }
    }
    __syncthreads();
#pragma unroll
    for (int mt = 0; mt < 2; mt++){
      float4 q0 = *(const float4*)&l2s[wr*32 + mt*16 + g][0];
      float4 q1 = *(const float4*)&l2s[wr*32 + mt*16 + g + 8][0];
      float s0 = (q0.x + q0.y) + (q0.z + q0.w);
      float s1 = (q1.x + q1.y) + (q1.z + q1.w);
      scale[mt][0] = 1.f / fmaxf(sqrtf(s0), 1e-12f);
      scale[mt][1] = 1.f / fmaxf(sqrtf(s1), 1e-12f);
    }
  }

#pragma unroll
  for (int mt = 0; mt < 2; mt++){
    int m = m0 + wr*32 + mt*16 + g;
    int b = m >> 8, t = m & 255;
#pragma unroll
    for (int nt = 0; nt < 4; nt++){
      int d = wn*32 + nt*8 + cq*2;
      size_t off = ((size_t)((b*NH + h)*TT + t))*HD + d;
      *(float2*)&DST[off] = make_float2(v[mt][nt][0]*scale[mt][0],
                                        v[mt][nt][1]*scale[mt][0]);
      *(float2*)&DST[off + 8*HD] = make_float2(v[mt][nt][2]*scale[mt][1],
                                               v[mt][nt][3]*scale[mt][1]);
    }
  }
}

// ------------------------- K2: chunk sums + scan fused ------------------------
__global__ void __launch_bounds__(256,4) k_chunkscan(){
  int vslab = blockIdx.x, bh = blockIdx.y;
  int tid = threadIdx.x;
  int i  = vslab*16 + (tid >> 4);
  int j0 = (tid & 15) * 8;
  __shared__ __align__(16) float ks[CS][HD], vs[CS][HD];
  __shared__ float coef[CS];
  __shared__ float dcs;
  float ckk[8], ckv[8];
#pragma unroll
  for (int u = 0; u < 8; u++){ ckk[u] = 0.f; ckv[u] = 0.f; }

  for (int c = 0; c < NC; c++){
    if (c) __syncthreads();
    {
      const float4* Kp = (const float4*)(g_K + (size_t)(bh*TT + c*CS)*HD);
      const float4* Vp = (const float4*)(g_V + (size_t)(bh*TT + c*CS)*HD);
      ((float4*)ks)[tid] = Kp[tid];
      ((float4*)vs)[tid] = Vp[tid];
    }
    if (tid < CS){
      float s = 0.f;
      for (int u = tid + 1; u < CS; u++) s += g_g[bh*TT + c*CS + u];
      coef[tid] = g_beta[bh*TT + c*CS + tid] * expf(s);
    }
    if (tid == 8){
      float s = 0.f;
      for (int u = 0; u < CS; u++) s += g_g[bh*TT + c*CS + u];
      dcs = expf(s);
    }
    __syncthreads();
    float dc = dcs;
#pragma unroll
    for (int u = 0; u < 8; u++){ ckk[u] *= dc; ckv[u] *= dc; }
#pragma unroll
    for (int s = 0; s < CS; s++){
      float ki = ks[s][i] * coef[s];
      float4 ka = *(const float4*)&ks[s][j0];
      float4 kb = *(const float4*)&ks[s][j0+4];
      float4 va = *(const float4*)&vs[s][j0];
      float4 vb = *(const float4*)&vs[s][j0+4];
      ckk[0] += ki*ka.x; ckk[1] += ki*ka.y; ckk[2] += ki*ka.z; ckk[3] += ki*ka.w;
      ckk[4] += ki*kb.x; ckk[5] += ki*kb.y; ckk[6] += ki*kb.z; ckk[7] += ki*kb.w;
      ckv[0] += ki*va.x; ckv[1] += ki*va.y; ckv[2] += ki*va.z; ckv[3] += ki*va.w;
      ckv[4] += ki*vb.x; ckv[5] += ki*vb.y; ckv[6] += ki*vb.z; ckv[7] += ki*vb.w;
    }
    size_t base = ((size_t)(bh*NC + c) << 14) + (size_t)i*HD + j0;
    *(float4*)&g_Skk[base]   = make_float4(ckk[0], ckk[1], ckk[2], ckk[3]);
    *(float4*)&g_Skk[base+4] = make_float4(ckk[4], ckk[5], ckk[6], ckk[7]);
    *(float4*)&g_Skv[base]   = make_float4(ckv[0], ckv[1], ckv[2], ckv[3]);
    *(float4*)&g_Skv[base+4] = make_float4(ckv[4], ckv[5], ckv[6], ckv[7]);
  }
}

// ------------------------- K3: batched 8-RHS CG solve (256 thr, 2 CTAs/SM) ----
#define PHASE_A(MSM) do { \
  ull y0a=0ull, y0b=0ull, y0c=0ull, y0d=0ull; \
  ull y1a=0ull, y1b=0ull, y1c=0ull, y1d=0ull; \
  _Pragma("unroll") \
  for (int jj = 0; jj < 32; jj++){ \
    ulonglong2 pA = *(const ulonglong2*)&P[mq*32+jj][0]; \
    ulonglong2 pB = *(const ulonglong2*)&P[mq*32+jj][4]; \
    ull h0 = bcast2(hk[jj]); \
    ull h1 = bcast2(hk[32+jj]); \
    ffma2(y0a, h0, pA.x); ffma2(y0b, h0, pA.y); ffma2(y0c, h0, pB.x); ffma2(y0d, h0, pB.y); \
    ffma2(y1a, h1, pA.x); ffma2(y1b, h1, pA.y); ffma2(y1c, h1, pB.x); ffma2(y1d, h1, pB.y); \
  } \
  *(ulonglong2*)&part[mq][mi][0] = make_ulonglong2(y0a, y0b); \
  *(ulonglong2*)&part[mq][mi][4] = make_ulonglong2(y0c, y0d); \
  *(ulonglong2*)&part[mq][mi+64][0] = make_ulonglong2(y1a, y1b); \
  *(ulonglong2*)&part[mq][mi+64][4] = make_ulonglong2(y1c, y1d); \
  { float4 kv_ = *(const float4*)&MSM[warp][lane*4]; \
    _Pragma("unroll") \
    for (int t_ = 0; t_ < 8; t_++){ \
      float4 pv_ = *(const float4*)&PT[t_][lane*4]; \
      float pd_ = kv_.x*pv_.x + kv_.y*pv_.y + kv_.z*pv_.z + kv_.w*pv_.w; \
      pd_ = warp_sum(pd_); \
      if (lane == 0) dots[t_][warp] = pd_; \
    } } \
} while(0)

#define ASM4(OUT) do { \
  float4 ya_ = make_float4(0.f, 0.f, 0.f, 0.f); \
  _Pragma("unroll") \
  for (int q2 = 0; q2 < 4; q2++){ \
    float4 pr_ = *(const float4*)&part[q2][si][t0]; \
    ya_.x += pr_.x; ya_.y += pr_.y; ya_.z += pr_.z; ya_.w += pr_.w; \
  } \
  float yarr_[4] = {ya_.x, ya_.y, ya_.z, ya_.w}; \
  _Pragma("unroll") \
  for (int u = 0; u < 4; u++){ \
    int t_ = t0 + u; \
    float a_ = cdec[t_] * yarr_[u]; \
    float4 d0_ = *(const float4*)&dots[t_][0]; \
    float4 d1_ = *(const float4*)&dots[t_][4]; \
    float4 w0_ = *(const float4*)&Wc[t_][0]; \
    float4 w1_ = *(const float4*)&Wc[t_][4]; \
    a_ += (w0_.x*d0_.x)*ksi[0] + (w0_.y*d0_.y)*ksi[1] \
        + (w0_.z*d0_.z)*ksi[2] + (w0_.w*d0_.w)*ksi[3] \
        + (w1_.x*d1_.x)*ksi[4] + (w1_.y*d1_.y)*ksi[5] \
        + (w1_.z*d1_.z)*ksi[6] + (w1_.w*d1_.w)*ksi[7]; \
    OUT[u] = a_; \
  } \
} while(0)

__global__ void __launch_bounds__(256,2) k_solve(const float* __restrict__ lp,
                                                 const float* __restrict__ onw){
  int c = blockIdx.x, bh = blockIdx.y;
  int b = bh >> 4, h = bh & 15;
  int tid = threadIdx.x;
  int si = tid & 127, sg2 = tid >> 7, lane = tid & 31, warp = tid >> 5;
  int mi = tid & 63, mq = tid >> 6;
  int g0 = bh*TT + c*CS;
  int t0 = sg2*4;

  __shared__ __align__(16) float Ksm[CS][HD], Vsm[CS][HD], Qsm[CS][HD];
  __shared__ __align__(16) float P[HD][12];
  __shared__ __align__(16) float PT[CS][HD+4];
  __shared__ __align__(16) float part[4][HD][12];
  __shared__ __align__(16) float dots[CS][CS];
  __shared__ __align__(16) float Wc[CS][CS];
  __shared__ float cdec[CS];
  __shared__ float lam[HD], dg[HD], gsm[CS], bsm[CS];
  __shared__ __align__(16) float wredA[4][8];
  __shared__ __align__(16) float wredB[4][8];

  {
    const float4* Kp = (const float4*)(g_K + (size_t)g0*HD);
    const float4* Vp = (const float4*)(g_V + (size_t)g0*HD);
    const float4* Qp = (const float4*)(g_Q + (size_t)g0*HD);
    ((float4*)Ksm)[tid] = Kp[tid];
    ((float4*)Qsm)[tid] = Qp[tid];
    ((float4*)Vsm)[tid] = Vp[tid];
  }
  if (tid >= 128 && tid < 136){ gsm[tid-128] = g_g[g0 + tid-128]; bsm[tid-128] = g_beta[g0 + tid-128]; }
  if (tid < 128){
    float zz = lp[h*HD + tid];
    float sp = (zz > 20.f) ? zz : log1pf(expf(zz));
    lam[tid] = sp + 0.25f;
  }
  float hk[64];
  if (c == 0){
#pragma unroll
    for (int jj = 0; jj < 64; jj++) hk[jj] = 0.f;
  } else {
    size_t base = ((size_t)(bh*NC + (c-1)) << 14) + mq*32;
#pragma unroll
    for (int jj = 0; jj < 32; jj += 4){
      float4 a = *(const float4*)&g_Skk[base + (size_t)mi*HD + jj];
      hk[jj] = a.x; hk[jj+1] = a.y; hk[jj+2] = a.z; hk[jj+3] = a.w;
      float4 a2 = *(const float4*)&g_Skk[base + (size_t)(mi+64)*HD + jj];
      hk[32+jj] = a2.x; hk[33+jj] = a2.y; hk[34+jj] = a2.z; hk[35+jj] = a2.w;
    }
  }
  if (mq == (mi >> 5))       dg[mi]      = hk[mi & 31];
  if (mq == 2 + (mi >> 5))   dg[mi + 64] = hk[32 + (mi & 31)];
  __syncthreads();

  if (tid < 64){
    int t_ = tid >> 3, s_ = tid & 7;
    float w = 0.f;
    if (s_ <= t_){
      float s = 0.f;
      for (int u = s_+1; u <= t_; u++) s += gsm[u];
      w = bsm[s_] * expf(s);
    }
    Wc[t_][s_] = w;
  }
  if (tid >= 64 && tid < 72){
    int t_ = tid - 64;
    float s = 0.f;
    for (int u = 0; u <= t_; u++) s += gsm[u];
    cdec[t_] = expf(s);
  }
  __syncthreads();

  float ksi[CS];
#pragma unroll
  for (int s = 0; s < CS; s++) ksi[s] = Ksm[s][si];
  float xv[4], rv[4], pv[4], dloc[4], qv[4];
  unsigned dmask = 0;
#pragma unroll
  for (int u = 0; u < 4; u++){
    int t = t0 + u;
    float diag = cdec[t]*dg[si] + lam[si];
#pragma unroll
    for (int s = 0; s < CS; s++) diag += Wc[t][s] * ksi[s] * ksi[s];
    float x = Qsm[t][si] / (diag + 1e-8f);
    xv[u] = x; P[si][t] = x; PT[t][si] = x;
  }
  __syncthreads();

  PHASE_A(Ksm);
  __syncthreads();
  {
    float av[4];
    ASM4(av);
#pragma unroll
    for (int u = 0; u < 4; u++){
      int t = t0 + u;
      float r = Qsm[t][si] - (av[u] + lam[si]*xv[u]);
      rv[u] = r; pv[u] = r;
      float rr = warp_sum(r*r);
      if (lane == 0) wredA[u][warp] = rr;
      P[si][t] = r; PT[t][si] = r;
    }
  }
  group_bar(sg2);
#pragma unroll
  for (int u = 0; u < 4; u++){
    float4 wv = *(const float4*)&wredA[u][sg2*4];
    dloc[u] = (wv.x + wv.y) + (wv.z + wv.w);
  }
  __syncthreads();

  for (int it = 0; it < NCG; it++){
    PHASE_A(Ksm);
    __syncthreads();
    {
      ASM4(qv);
#pragma unroll
      for (int u = 0; u < 4; u++){
        qv[u] += lam[si] * pv[u];
        float pq = warp_sum(pv[u] * qv[u]);
        if (lane == 0) wredA[u][warp] = pq;
      }
    }
    group_bar(sg2);
#pragma unroll
    for (int u = 0; u < 4; u++){
      float4 wv = *(const float4*)&wredA[u][sg2*4];
      float pq = (wv.x + wv.y) + (wv.z + wv.w);
      if (dloc[u] < 1e-10f) dmask |= 1u << u;
      if (fabsf(pq) < 1e-10f) dmask |= 1u << u;
      float alpha = (dmask >> u & 1u) ? 0.f : dloc[u] / pq;
      xv[u] += alpha * pv[u];
      rv[u] -= alpha * qv[u];
      float rr = warp_sum(rv[u] * rv[u]);
      if (lane == 0) wredB[u][warp] = rr;
    }
    group_bar(sg2);
#pragma unroll
    for (int u = 0; u < 4; u++){
      int t = t0 + u;
      float4 wv = *(const float4*)&wredB[u][sg2*4];
      float dn = (wv.x + wv.y) + (wv.z + wv.w);
      if (!(dmask >> u & 1u)){
        float bet = dn / dloc[u];
        dloc[u] = dn;
        pv[u] = rv[u] + bet * pv[u];
      }
      P[si][t] = pv[u]; PT[t][si] = pv[u];
    }
    __syncthreads();
  }

#pragma unroll
  for (int u = 0; u < 4; u++){
    int t = t0 + u;
    P[si][t] = xv[u]; PT[t][si] = xv[u];
  }
  if (c == 0){
#pragma unroll
    for (int jj = 0; jj < 64; jj++) hk[jj] = 0.f;
  } else {
    size_t base = ((size_t)(bh*NC + (c-1)) << 14) + mq*32;
#pragma unroll
    for (int jj = 0; jj < 32; jj += 4){
      float4 a = *(const float4*)&g_Skv[base + (size_t)mi*HD + jj];
      hk[jj] = a.x; hk[jj+1] = a.y; hk[jj+2] = a.z; hk[jj+3] = a.w;
      float4 a2 = *(const float4*)&g_Skv[base + (size_t)(mi+64)*HD + jj];
      hk[32+jj] = a2.x; hk[33+jj] = a2.y; hk[34+jj] = a2.z; hk[35+jj] = a2.w;
    }
  }
  __syncthreads();
  PHASE_A(Vsm);
  __syncthreads();
  float ov[4];
  ASM4(ov);
#pragma unroll
  for (int u = 0; u < 4; u++){
    float ss = warp_sum(ov[u]*ov[u]);
    if (lane == 0) wredA[u][warp] = ss;
  }
  group_bar(sg2);
  float wnv = onw[si];
#pragma unroll
  for (int u = 0; u < 4; u++){
    int t = t0 + u;
    float4 wv = *(const float4*)&wredA[u][sg2*4];
    float ms = ((wv.x + wv.y) + (wv.z + wv.w)) * (1.f/128.f);
    float rms = sqrtf(ms + 1e-6f);
    int ts = c*CS + t;
    g_Of[(size_t)(b*TT + ts)*HID + h*HD + si] = ov[u] / rms * wnv;
  }
}

// ------------------------- K4: output projection (3xTF32, dbl-buf dyn-smem) ---
__global__ void __launch_bounds__(256) k_out(const float* __restrict__ Wo,
                                             float* __restrict__ out){
  extern __shared__ __align__(16) char smem_raw[];
  uint32_t (*Ah)[64][20]  = (uint32_t(*)[64][20])(smem_raw + AH_OFF);
  uint32_t (*Al)[64][20]  = (uint32_t(*)[64][20])(smem_raw + AL_OFF);
  uint32_t (*Bh)[16][136] = (uint32_t(*)[16][136])(smem_raw + BH_OFF);
  uint32_t (*Bl)[16][136] = (uint32_t(*)[16][136])(smem_raw + BL_OFF);

  int tid = threadIdx.x;
  int lane = tid & 31, warp = tid >> 5;
  int wr = warp >> 2, wn = warp & 3;
  int g = lane >> 2, cq = lane & 3;
  int m0 = blockIdx.y * 64;
  int n0 = blockIdx.x * 128;

  float acc[2][4][4];
#pragma unroll
  for (int mt = 0; mt < 2; mt++)
#pragma unroll
    for (int nt = 0; nt < 4; nt++)
#pragma unroll
      for (int j = 0; j < 4; j++) acc[mt][nt][j] = 0.f;

  int am = tid >> 2, ak = (tid & 3) * 4;
  int bk0 = tid >> 5, bn0 = (tid & 31) * 4;
  float4 pa, pb[2];
  pa = *(const float4*)&g_Of[(size_t)(m0 + am)*HID + ak];
#pragma unroll
  for (int p = 0; p < 2; p++)
    pb[p] = *(const float4*)&Wo[(size_t)(bk0 + p*8)*HID + n0 + bn0];

  for (int kb = 0; kb < HID; kb += 16){
    int cur = (kb >> 4) & 1;
    {
      float vv[4] = {pa.x, pa.y, pa.z, pa.w};
      uint32_t hi[4], lo[4];
#pragma unroll
      for (int e = 0; e < 4; e++){
        hi[e] = f2tf32(vv[e]);
        lo[e] = f2tf32(vv[e] - __uint_as_float(hi[e]));
      }
      *(uint4*)&Ah[cur][am][ak] = make_uint4(hi[0], hi[1], hi[2], hi[3]);
      *(uint4*)&Al[cur][am][ak] = make_uint4(lo[0], lo[1], lo[2], lo[3]);
#pragma unroll
      for (int p = 0; p < 2; p++){
        float wv[4] = {pb[p].x, pb[p].y, pb[p].z, pb[p].w};
#pragma unroll
        for (int e = 0; e < 4; e++){
          hi[e] = f2tf32(wv[e]);
          lo[e] = f2tf32(wv[e] - __uint_as_float(hi[e]));
        }
        *(uint4*)&Bh[cur][bk0 + p*8][bn0] = make_uint4(hi[0], hi[1], hi[2], hi[3]);
        *(uint4*)&Bl[cur][bk0 + p*8][bn0] = make_uint4(lo[0], lo[1], lo[2], lo[3]);
      }
    }
    __syncthreads();
    if (kb + 16 < HID){
      pa = *(const float4*)&g_Of[(size_t)(m0 + am)*HID + kb + 16 + ak];
#pragma unroll
      for (int p = 0; p < 2; p++)
        pb[p] = *(const float4*)&Wo[(size_t)(kb + 16 + bk0 + p*8)*HID + n0 + bn0];
    }
#pragma unroll
    for (int ks = 0; ks < 2; ks++){
      int k0 = ks*8 + cq;
      uint32_t ah[2][4], al[2][4];
#pragma unroll
      for (int mt = 0; mt < 2; mt++){
        int mb = wr*32 + mt*16;
        ah[mt][0] = Ah[cur][mb+g][k0];   ah[mt][1] = Ah[cur][mb+g+8][k0];
        ah[mt][2] = Ah[cur][mb+g][k0+4]; ah[mt][3] = Ah[cur][mb+g+8][k0+4];
        al[mt][0] = Al[cur][mb+g][k0];   al[mt][1] = Al[cur][mb+g+8][k0];
        al[mt][2] = Al[cur][mb+g][k0+4]; al[mt][3] = Al[cur][mb+g+8][k0+4];
      }
#pragma unroll
      for (int nt = 0; nt < 4; nt++){
        int nb = wn*32 + nt*8;
        uint32_t bh0 = Bh[cur][k0][nb+g], bh1 = Bh[cur][k0+4][nb+g];
        uint32_t bl0 = Bl[cur][k0][nb+g], bl1 = Bl[cur][k0+4][nb+g];
#pragma unroll
        for (int mt = 0; mt < 2; mt++){
          MMA_TF32(acc[mt][nt], ah[mt][0], ah[mt][1], ah[mt][2], ah[mt][3], bl0, bl1);
          MMA_TF32(acc[mt][nt], al[mt][0], al[mt][1], al[mt][2], al[mt][3], bh0, bh1);
          MMA_TF32(acc[mt][nt], ah[mt][0], ah[mt][1], ah[mt][2], ah[mt][3], bh0, bh1);
        }
      }
    }
    // no trailing sync: next store targets the other buffer
  }

#pragma unroll
  for (int mt = 0; mt < 2; mt++){
    int m = m0 + wr*32 + mt*16 + g;
#pragma unroll
    for (int nt = 0; nt < 4; nt++){
      int cc = n0 + wn*32 + nt*8 + cq*2;
      *(float2*)&out[(size_t)m*HID + cc]     = make_float2(acc[mt][nt][0], acc[mt][nt][1]);
      *(float2*)&out[(size_t)(m+8)*HID + cc] = make_float2(acc[mt][nt][2], acc[mt][nt][3]);
    }
  }
}

// ------------------------- launcher -------------------------
extern "C" void kernel_launch(void* const* d_in, const int* in_sizes, int n_in,
                              void* d_out, int out_size){
  const float* x    = (const float*)d_in[0];
  const float* Wq   = (const float*)d_in[1];
  const float* Wk   = (const float*)d_in[2];
  const float* Wv   = (const float*)d_in[3];
  const float* Wa   = (const float*)d_in[4];
  const float* ba   = (const float*)d_in[5];
  const float* Wb   = (const float*)d_in[6];
  const float* bb   = (const float*)d_in[7];
  const float* lpar = (const float*)d_in[8];
  const float* onw  = (const float*)d_in[9];
  const float* Wo   = (const float*)d_in[10];
  float* out = (float*)d_out;

  cudaFuncSetAttribute(k_qkv, cudaFuncAttributeMaxDynamicSharedMemorySize, QKV_SMEM);
  cudaFuncSetAttribute(k_out, cudaFuncAttributeMaxDynamicSharedMemorySize, OUT_SMEM);

  k_qkv<<<dim3(16, 8, 4), 256, QKV_SMEM>>>(x, Wq, Wk, Wv, Wa, ba, Wb, bb);
  k_chunkscan<<<dim3(8, BH), 256>>>();
  k_solve<<<dim3(NC, BH), 256>>>(lpar, onw);
  k_out<<<dim3(16, 8), 256, OUT_SMEM>>>(Wo, out);
}